// round 13
// baseline (speedup 1.0000x reference)
#include <cuda_runtime.h>
#include <cuda_fp16.h>
#include <cstdint>

// ---------------- problem constants ----------------
#define Bsz 8
#define Tsz 1024
#define Msz (Bsz*Tsz)        // 8192
#define DM  256
#define DI  512
#define DS  16
#define NCLS 60
#define KF  256              // 225 padded to 256 (zero-filled)
#define CH  32               // scan chunk

// ---------------- device scratch ----------------
__device__ __half g_fk_h[Msz*KF];          // features fp16 (A of embed)
__device__ float  g_feat[Msz*DM];
__device__ float  g_hn[Msz*DM];
__device__ __half g_hn_h[Msz*DM];          // A of in_proj
__device__ float  g_xz[(size_t)Msz*1024];
__device__ float  g_xmc[Msz*DI];
__device__ __half g_xm_h[Msz*DI];          // A of x_proj
__device__ float  g_dbl[Msz*48];
__device__ __half g_dt_h[Msz*16];          // dt fp16 (fused from x_proj epilogue)
__device__ __half g_y_h[Msz*DI];           // A of out_proj
// weights fp16 hi/lo (padded)
__device__ __half g_wemb_h[DM*KF],  g_wemb_l[DM*KF];     // 256 x 256
__device__ __half g_win_h[1024*DM], g_win_l[1024*DM];    // 1024 x 256
__device__ __half g_wxp_h[64*DI],   g_wxp_l[64*DI];      // 48->64 x 512
__device__ __half g_wout_h[DM*DI],  g_wout_l[DM*DI];     // 256 x 512

__device__ __forceinline__ float softplusf(float v){
    return v > 20.f ? v : log1pf(expf(v));
}
__device__ __forceinline__ float siluf(float v){
    return v / (1.f + __expf(-v));
}
__device__ __forceinline__ void splith(float v, __half& h, __half& l){
    h = __float2half_rn(v);
    l = __float2half_rn(v - __half2float(h));
}
__device__ __forceinline__ uint32_t smem_u32(const void* p){
    uint32_t a;
    asm("{ .reg .u64 t; cvta.to.shared.u64 t, %1; cvt.u32.u64 %0, t; }" : "=r"(a) : "l"(p));
    return a;
}
__device__ __forceinline__ void cp16(uint32_t dst, const void* src){
    asm volatile("cp.async.cg.shared.global [%0], [%1], 16;" :: "r"(dst), "l"(src));
}
__device__ __forceinline__ void mma16816(float* d, const uint32_t* a, const uint32_t* b){
    asm volatile(
        "mma.sync.aligned.m16n8k16.row.col.f32.f16.f16.f32 "
        "{%0,%1,%2,%3}, {%4,%5,%6,%7}, {%8,%9}, {%0,%1,%2,%3};"
        : "+f"(d[0]), "+f"(d[1]), "+f"(d[2]), "+f"(d[3])
        : "r"(a[0]), "r"(a[1]), "r"(a[2]), "r"(a[3]), "r"(b[0]), "r"(b[1]));
}
__device__ __forceinline__ void ldsm4(uint32_t* r, uint32_t addr){
    asm volatile("ldmatrix.sync.aligned.m8n8.x4.shared.b16 {%0,%1,%2,%3}, [%4];"
        : "=r"(r[0]), "=r"(r[1]), "=r"(r[2]), "=r"(r[3]) : "r"(addr));
}
__device__ __forceinline__ void ldsm2(uint32_t* r, uint32_t addr){
    asm volatile("ldmatrix.sync.aligned.m8n8.x2.shared.b16 {%0,%1}, [%2];"
        : "=r"(r[0]), "=r"(r[1]) : "r"(addr));
}

// ---------------- merged prep: weight splits + feature construction ----------------
__global__ void prep_kernel(const float* __restrict__ x,
                            const float* __restrict__ embed_w,
                            const float* __restrict__ in_proj_w,
                            const float* __restrict__ x_proj_w,
                            const float* __restrict__ out_proj_w){
    const int b = blockIdx.x;
    const int t = threadIdx.x;
    if (b < 256){                               // embed_w: 256 x 225 -> 256 x 256 hi/lo
        int i = b*256 + t;
        int n = i >> 8, k = i & 255;
        float v = (k < 225) ? embed_w[n*225 + k] : 0.f;
        __half h, l; splith(v, h, l);
        g_wemb_h[i] = h; g_wemb_l[i] = l;
    } else if (b < 1280){                       // in_proj_w: 1024 x 256
        int i = (b-256)*256 + t;
        __half h, l; splith(in_proj_w[i], h, l);
        g_win_h[i] = h; g_win_l[i] = l;
    } else if (b < 1408){                       // x_proj_w: 48 x 512 -> 64 x 512
        int i = (b-1280)*256 + t;
        int n = i >> 9;
        float v = (n < 48) ? x_proj_w[i] : 0.f;
        __half h, l; splith(v, h, l);
        g_wxp_h[i] = h; g_wxp_l[i] = l;
    } else if (b < 1920){                       // out_proj_w: 256 x 512
        int i = (b-1408)*256 + t;
        __half h, l; splith(out_proj_w[i], h, l);
        g_wout_h[i] = h; g_wout_l[i] = l;
    } else {                                    // features: Msz*25 items
        int i = (b-1920)*256 + t;
        if (i >= Msz*25) return;
        int j = i % 25;
        int m = i / 25;
        int tt = m & (Tsz-1);
        const float* xr  = x + (size_t)m*75;
        const float* xr1 = xr - 75;
        const float* xr2 = xr - 150;
        size_t ob = (size_t)m*KF + j*9;
        #pragma unroll
        for (int c = 0; c < 3; c++){
            float p0 = xr[j*3+c]  - xr[c];
            float p1 = (tt>=1) ? (xr1[j*3+c] - xr1[c]) : 0.f;
            float p2 = (tt>=2) ? (xr2[j*3+c] - xr2[c]) : 0.f;
            float vel   = (tt>=1) ? (p0 - p1) : 0.f;
            float velm1 = (tt>=2) ? (p1 - p2) : 0.f;
            float acc   = (tt>=1) ? (vel - velm1) : 0.f;
            g_fk_h[ob+c]   = __float2half_rn(p0);
            g_fk_h[ob+3+c] = __float2half_rn(vel);
            g_fk_h[ob+6+c] = __float2half_rn(acc);
        }
        if (j == 0){
            __half z = __float2half_rn(0.f);
            for (int k = 225; k < KF; k++) g_fk_h[(size_t)m*KF + k] = z;
        }
    }
}

// ---------------- fp16 2-pass tensor-core GEMM (NT): C = A @ W^T ----------------
// Tile MT x NT, block 256 thr (8 warps, 2M x 4N). KC=32 for high occupancy.
template<int MT, int NT, int KC>
__global__ __launch_bounds__(256) void gemm_h(
    int K, int N,
    const __half* __restrict__ A_, int lda,
    const __half* __restrict__ Wh_, const __half* __restrict__ Wl_, int ldw,
    float* __restrict__ C, int ldc,
    const float* __restrict__ bias,
    const float* __restrict__ addC, int ldadd,
    int act, __half* __restrict__ dtout)
{
    extern __shared__ char smem[];
    constexpr int LDT = KC + 8;                   // fp16 elems per padded row
    constexpr int SBUF = (MT + 2*NT)*LDT;         // elems per buffer
    constexpr int C8 = KC/8;                      // 16B chunks per row
    constexpr int MW = MT/32;                     // 16-row m-tiles per warp
    const uint32_t sb = smem_u32(smem);
    const int tid = threadIdx.x, lane = tid & 31, warp = tid >> 5;
    const int bm = blockIdx.y * MT;
    const int bn = blockIdx.x * NT;
    const int nv = min(NT, N - bn);
    const int wm = (warp & 1) * (MT/2);
    const int wn = (warp >> 1) * (NT/4);

    float acc[MW][2][4];
    #pragma unroll
    for (int mt = 0; mt < MW; mt++)
        #pragma unroll
        for (int nt = 0; nt < 2; nt++)
            #pragma unroll
            for (int i = 0; i < 4; i++) acc[mt][nt][i] = 0.f;

    const int a_row  = wm + (lane & 15);
    const int a_colb = (lane >> 4) * 8;
    const int b_row  = wn + (lane & 7);
    const int b_colb = ((lane >> 3) & 1) * 8;

    const int NC = K / KC;

    auto load_chunk = [&](int c, int bf){
        uint32_t base = sb + (uint32_t)(bf * SBUF * 2);
        const size_t koff = (size_t)c * KC;
        #pragma unroll 2
        for (int idx = tid; idx < MT*C8; idx += 256){
            int row = idx / C8, c8 = idx - row*C8;
            cp16(base + (uint32_t)((row*LDT + c8*8) * 2),
                 A_ + (size_t)(bm + row)*lda + koff + c8*8);
        }
        #pragma unroll 2
        for (int idx = tid; idx < NT*C8; idx += 256){
            int row = idx / C8, c8 = idx - row*C8;
            uint32_t d = base + (uint32_t)(((MT + row)*LDT + c8*8) * 2);
            size_t s = (size_t)(bn + row)*ldw + koff + c8*8;
            cp16(d,              Wh_ + s);
            cp16(d + NT*LDT*2,   Wl_ + s);
        }
    };

    int buf = 0;
    load_chunk(0, 0);
    asm volatile("cp.async.commit_group;" ::: "memory");
    for (int c = 0; c < NC; c++){
        if (c + 1 < NC) load_chunk(c + 1, buf ^ 1);
        asm volatile("cp.async.commit_group;" ::: "memory");
        if (c + 1 < NC) asm volatile("cp.async.wait_group 1;" ::: "memory");
        else            asm volatile("cp.async.wait_group 0;" ::: "memory");
        __syncthreads();

        uint32_t abase = sb + (uint32_t)(buf * SBUF * 2);
        #pragma unroll
        for (int kk = 0; kk < KC; kk += 16){
            uint32_t a[MW][4];
            #pragma unroll
            for (int mt = 0; mt < MW; mt++)
                ldsm4(a[mt], abase + (uint32_t)(((a_row + mt*16)*LDT + kk + a_colb) * 2));
            uint32_t bh[2][2], bl[2][2];
            #pragma unroll
            for (int nt = 0; nt < 2; nt++){
                uint32_t bd = abase + (uint32_t)(((MT + b_row + nt*8)*LDT + kk + b_colb) * 2);
                ldsm2(bh[nt], bd);
                ldsm2(bl[nt], bd + NT*LDT*2);
            }
            #pragma unroll
            for (int mt = 0; mt < MW; mt++)
                #pragma unroll
                for (int nt = 0; nt < 2; nt++){
                    mma16816(acc[mt][nt], a[mt], bh[nt]);
                    mma16816(acc[mt][nt], a[mt], bl[nt]);
                }
        }
        __syncthreads();
        buf ^= 1;
    }

    // epilogue: fragment -> global, fused bias / softplus / residual / dt-split
    #pragma unroll
    for (int mt = 0; mt < MW; mt++){
        #pragma unroll
        for (int i = 0; i < 4; i++){
            int m = bm + wm + mt*16 + (lane >> 2) + (i >> 1)*8;
            #pragma unroll
            for (int nt = 0; nt < 2; nt++){
                int n = wn + nt*8 + (lane & 3)*2 + (i & 1);
                if (n < nv){
                    int gn = bn + n;
                    float v = acc[mt][nt][i];
                    if (bias) v += bias[gn];
                    if (act)  v  = softplusf(v);
                    if (addC) v += addC[(size_t)m*ldadd + gn];
                    C[(size_t)m*ldc + gn] = v;
                    if (dtout && gn < 16) dtout[(size_t)m*16 + gn] = __float2half_rn(v);
                }
            }
        }
    }
}

// ---------------- layernorm, warp-per-row (256 cols) ----------------
__global__ __launch_bounds__(256) void ln_kernel(
    const float* __restrict__ in, const float* __restrict__ g,
    const float* __restrict__ bta, float* __restrict__ outf,
    __half* __restrict__ oh, int mode)
{
    int row  = blockIdx.x*8 + (threadIdx.x >> 5);
    int lane = threadIdx.x & 31;
    const float* p = in + (size_t)row*DM + lane*8;
    float4 v0 = *(const float4*)p;
    float4 v1 = *(const float4*)(p + 4);
    float va[8] = {v0.x,v0.y,v0.z,v0.w,v1.x,v1.y,v1.z,v1.w};
    float s = 0.f, q = 0.f;
    #pragma unroll
    for (int i = 0; i < 8; i++){ s += va[i]; q = fmaf(va[i], va[i], q); }
    #pragma unroll
    for (int o = 16; o; o >>= 1){
        s += __shfl_xor_sync(0xffffffffu, s, o);
        q += __shfl_xor_sync(0xffffffffu, q, o);
    }
    float mu  = s * (1.f/256.f);
    float var = q * (1.f/256.f) - mu*mu;
    float inv = rsqrtf(var + 1e-5f);
    float4 g0 = *(const float4*)(g + lane*8);
    float4 g1 = *(const float4*)(g + lane*8 + 4);
    float4 b0 = *(const float4*)(bta + lane*8);
    float4 b1 = *(const float4*)(bta + lane*8 + 4);
    float ga[8] = {g0.x,g0.y,g0.z,g0.w,g1.x,g1.y,g1.z,g1.w};
    float ba[8] = {b0.x,b0.y,b0.z,b0.w,b1.x,b1.y,b1.z,b1.w};
    float r[8];
    #pragma unroll
    for (int i = 0; i < 8; i++) r[i] = (va[i] - mu) * inv * ga[i] + ba[i];
    if (mode == 0){
        float* o = outf + (size_t)row*DM + lane*8;
        *(float4*)o       = make_float4(r[0], r[1], r[2], r[3]);
        *(float4*)(o + 4) = make_float4(r[4], r[5], r[6], r[7]);
    } else {
        size_t ob = (size_t)row*DM + lane*8;
        #pragma unroll
        for (int i = 0; i < 8; i++) oh[ob + i] = __float2half_rn(r[i]);
    }
}

// ---------------- causal depthwise conv (k=4) + silu (fp32 + fp16 out) ----------------
__global__ void conv_silu_kernel(const float* __restrict__ cw, const float* __restrict__ cb){
    int i = blockIdx.x*blockDim.x + threadIdx.x;
    int d = i & (DI-1);
    int m = i >> 9;
    int t = m & (Tsz-1);
    float w0 = cw[d*4+0], w1 = cw[d*4+1], w2 = cw[d*4+2], w3 = cw[d*4+3];
    float a = cb[d];
    a = fmaf(w3, g_xz[(size_t)m*1024 + d], a);
    if (t >= 1) a = fmaf(w2, g_xz[(size_t)(m-1)*1024 + d], a);
    if (t >= 2) a = fmaf(w1, g_xz[(size_t)(m-2)*1024 + d], a);
    if (t >= 3) a = fmaf(w0, g_xz[(size_t)(m-3)*1024 + d], a);
    float sv = siluf(a);
    g_xmc[i] = sv;
    g_xm_h[i] = __float2half_rn(sv);
}

// ---------------- selective scan: SHFL-free, dt_proj fused, CH=32 ----------------
__global__ __launch_bounds__(128) void scan_kernel(
    const float* __restrict__ A_log, const float* __restrict__ Dp,
    const float* __restrict__ dt_w, const float* __restrict__ dt_b)
{
    __shared__ float s_dv [2][CH][8];
    __shared__ float s_uv [2][CH][8];
    __shared__ float s_res[2][CH][8];
    __shared__ float s_bc [2][CH][32];
    __shared__ float s_p  [CH][8][17];
    __shared__ float s_wdt[8][17];
    __shared__ float s_db[8];

    const int tid  = threadIdx.x;
    const int lane = tid & 31;
    const int warp = tid >> 5;
    const int b     = blockIdx.x >> 6;
    const int dbase = (blockIdx.x & 63) * 8;
    const int dloc  = warp*2 + (lane >> 4);
    const int d     = dbase + dloc;
    const int n     = lane & 15;

    const float a  = -expf(A_log[d*DS + n]);
    const size_t base = (size_t)b * Tsz;

    const int lt = tid >> 3;      // 0..15
    const int ld = tid & 7;       // 0..7
    const int bt = tid >> 5;      // 0..3
    const int bcc = tid & 31;
    const float DdR = Dp[dbase + ld];

    {
        int dd = tid >> 4, kk = tid & 15;
        s_wdt[dd][kk] = dt_w[(dbase + dd)*16 + kk];
        if (tid < 8) s_db[tid] = dt_b[dbase + tid];
    }
    __syncthreads();

    auto calc_dv = [&](size_t row)->float{
        const __half2* dp = (const __half2*)(g_dt_h + row*16);
        float s = s_db[ld];
        #pragma unroll
        for (int k = 0; k < 8; k++){
            float2 v = __half22float2(dp[k]);
            s = fmaf(v.x, s_wdt[ld][2*k],   s);
            s = fmaf(v.y, s_wdt[ld][2*k+1], s);
        }
        return softplusf(s);
    };

    {
        #pragma unroll
        for (int hh = 0; hh < 2; hh++){
            int rr = lt + hh*16;
            size_t row = base + rr;
            s_dv [0][rr][ld] = calc_dv(row);
            s_uv [0][rr][ld] = g_xmc[row*DI + dbase + ld];
            s_res[0][rr][ld] = g_xz [row*1024 + 512 + dbase + ld];
        }
        #pragma unroll
        for (int r = 0; r < 8; r++)
            s_bc[0][bt + r*4][bcc] = g_dbl[(base + bt + r*4)*48 + 16 + bcc];
    }
    __syncthreads();

    float h = 0.f;
    int buf = 0;
    for (int tcb = 0; tcb < Tsz; tcb += CH){
        const bool more = (tcb + CH) < Tsz;
        float r_dv[2], r_uv[2], r_res[2], r_bc[8];
        if (more){
            #pragma unroll
            for (int hh = 0; hh < 2; hh++){
                size_t row = base + tcb + CH + lt + hh*16;
                r_dv[hh]  = calc_dv(row);
                r_uv[hh]  = g_xmc[row*DI + dbase + ld];
                r_res[hh] = g_xz [row*1024 + 512 + dbase + ld];
            }
            #pragma unroll
            for (int r = 0; r < 8; r++)
                r_bc[r] = g_dbl[(base + tcb + CH + bt + r*4)*48 + 16 + bcc];
        }
        #pragma unroll
        for (int i = 0; i < CH; i++){
            float dv = s_dv[buf][i][dloc];
            float uv = s_uv[buf][i][dloc];
            float Bn = s_bc[buf][i][n];
            float Cn = s_bc[buf][i][16 + n];
            float dA = __expf(dv * a);
            h = fmaf(dA, h, dv * Bn * uv);
            s_p[i][dloc][n] = h * Cn;
        }
        __syncthreads();
        #pragma unroll
        for (int hh = 0; hh < 2; hh++){
            int rr = lt + hh*16;
            float s = 0.f;
            #pragma unroll
            for (int k = 0; k < 16; k++) s += s_p[rr][ld][k];
            float uv = s_uv[buf][rr][ld];
            float rv = s_res[buf][rr][ld];
            float yv = fmaf(uv, DdR, s) * siluf(rv);
            g_y_h[(base + tcb + rr)*DI + dbase + ld] = __float2half_rn(yv);
        }
        if (more){
            int nb = buf ^ 1;
            #pragma unroll
            for (int hh = 0; hh < 2; hh++){
                int rr = lt + hh*16;
                s_dv [nb][rr][ld] = r_dv[hh];
                s_uv [nb][rr][ld] = r_uv[hh];
                s_res[nb][rr][ld] = r_res[hh];
            }
            #pragma unroll
            for (int r = 0; r < 8; r++)
                s_bc[nb][bt + r*4][bcc] = r_bc[r];
        }
        __syncthreads();
        buf ^= 1;
    }
}

// ---------------- fused mean-pool + classifier head ----------------
__global__ __launch_bounds__(256) void poolfine_kernel(
    const float* __restrict__ fw, const float* __restrict__ fb,
    float* __restrict__ out)
{
    __shared__ float sp[DM];
    int b = blockIdx.x;
    int tid = threadIdx.x;
    const float* p = g_hn + (size_t)b*Tsz*DM + tid;
    float s0=0.f, s1=0.f, s2=0.f, s3=0.f;
    for (int t = 0; t < Tsz; t += 4){
        s0 += p[(size_t)(t+0)*DM];
        s1 += p[(size_t)(t+1)*DM];
        s2 += p[(size_t)(t+2)*DM];
        s3 += p[(size_t)(t+3)*DM];
    }
    sp[tid] = (s0+s1+s2+s3) * (1.f/1024.f);
    __syncthreads();
    int nn = tid >> 2;
    int q  = tid & 3;
    if (nn < NCLS){
        const float* wr = fw + nn*DM + q*64;
        const float* pr = sp + q*64;
        float s = 0.f;
        #pragma unroll
        for (int k = 0; k < 64; k++) s = fmaf(pr[k], wr[k], s);
        s += __shfl_xor_sync(0xffffffffu, s, 1);
        s += __shfl_xor_sync(0xffffffffu, s, 2);
        if (q == 0) out[b*NCLS + nn] = s + fb[nn];
    }
}

// ---------------- launch ----------------
extern "C" void kernel_launch(void* const* d_in, const int* in_sizes, int n_in,
                              void* d_out, int out_size)
{
    const float* x          = (const float*)d_in[0];
    const float* embed_w    = (const float*)d_in[1];
    const float* embed_b    = (const float*)d_in[2];
    const float* pre_g      = (const float*)d_in[3];
    const float* pre_b      = (const float*)d_in[4];
    const float* in_proj_w  = (const float*)d_in[5];
    const float* conv_w     = (const float*)d_in[6];
    const float* conv_b     = (const float*)d_in[7];
    const float* x_proj_w   = (const float*)d_in[8];
    const float* dt_proj_w  = (const float*)d_in[9];
    const float* dt_proj_b  = (const float*)d_in[10];
    const float* A_log      = (const float*)d_in[11];
    const float* Dp         = (const float*)d_in[12];
    const float* out_proj_w = (const float*)d_in[13];
    const float* post_g     = (const float*)d_in[14];
    const float* post_b     = (const float*)d_in[15];
    const float* fine_w     = (const float*)d_in[16];
    const float* fine_b     = (const float*)d_in[17];
    float* out = (float*)d_out;

    void *p_fk,*p_feat,*p_hn,*p_hnh,*p_xz,*p_xmh,*p_dbl,*p_dth,*p_yh,
         *p_wembh,*p_wembl,*p_winh,*p_winl,*p_wxph,*p_wxpl,*p_wouth,*p_woutl;
    cudaGetSymbolAddress(&p_fk, g_fk_h);
    cudaGetSymbolAddress(&p_feat, g_feat);   cudaGetSymbolAddress(&p_hn, g_hn);
    cudaGetSymbolAddress(&p_hnh, g_hn_h);
    cudaGetSymbolAddress(&p_xz, g_xz);       cudaGetSymbolAddress(&p_xmh, g_xm_h);
    cudaGetSymbolAddress(&p_dbl, g_dbl);     cudaGetSymbolAddress(&p_dth, g_dt_h);
    cudaGetSymbolAddress(&p_yh, g_y_h);
    cudaGetSymbolAddress(&p_wembh, g_wemb_h); cudaGetSymbolAddress(&p_wembl, g_wemb_l);
    cudaGetSymbolAddress(&p_winh, g_win_h);   cudaGetSymbolAddress(&p_winl, g_win_l);
    cudaGetSymbolAddress(&p_wxph, g_wxp_h);   cudaGetSymbolAddress(&p_wxpl, g_wxp_l);
    cudaGetSymbolAddress(&p_wouth, g_wout_h); cudaGetSymbolAddress(&p_woutl, g_wout_l);

    const int SM_G128 = 2 * ((128 + 128)*(32+8)) * 2;  // 40960 B
    const int SM_G64  = 2 * ((64  + 128)*(32+8)) * 2;  // 30720 B
    cudaFuncSetAttribute(gemm_h<128,64,32>, cudaFuncAttributeMaxDynamicSharedMemorySize, SM_G128);
    cudaFuncSetAttribute(gemm_h<64,64,32>,  cudaFuncAttributeMaxDynamicSharedMemorySize, SM_G64);

    // 1) merged prep (weight splits + features)
    prep_kernel<<<2720, 256>>>(x, embed_w, in_proj_w, x_proj_w, out_proj_w);

    // 2) embed GEMM (MT=64: 512 CTAs)
    gemm_h<64,64,32><<<dim3(DM/64, Msz/64), 256, SM_G64>>>(
        KF, DM,
        (const __half*)p_fk, KF,
        (const __half*)p_wembh, (const __half*)p_wembl, KF,
        (float*)p_feat, DM, embed_b, nullptr, 0, 0, nullptr);

    // 3) pre-LN -> fp16
    ln_kernel<<<Msz/8, 256>>>((const float*)p_feat, pre_g, pre_b,
        nullptr, (__half*)p_hnh, 1);

    // 4) in_proj GEMM (MT=128, ncu capture slot)
    gemm_h<128,64,32><<<dim3(1024/64, Msz/128), 256, SM_G128>>>(
        DM, 1024,
        (const __half*)p_hnh, DM,
        (const __half*)p_winh, (const __half*)p_winl, DM,
        (float*)p_xz, 1024, nullptr, nullptr, 0, 0, nullptr);

    // 5) depthwise conv + silu
    conv_silu_kernel<<<(Msz*DI)/256, 256>>>(conv_w, conv_b);

    // 6) x_proj GEMM (N=48, dt fused; MT=64: 128 CTAs)
    gemm_h<64,64,32><<<dim3(1, Msz/64), 256, SM_G64>>>(
        DI, 48,
        (const __half*)p_xmh, DI,
        (const __half*)p_wxph, (const __half*)p_wxpl, DI,
        (float*)p_dbl, 48, nullptr, nullptr, 0, 0, (__half*)p_dth);

    // 7) selective scan (dt_proj + softplus + gate fused, SHFL-free, CH=32)
    scan_kernel<<<Bsz*64, 128>>>(A_log, Dp, dt_proj_w, dt_proj_b);

    // 8) out_proj GEMM + residual (MT=64: 512 CTAs)
    gemm_h<64,64,32><<<dim3(DM/64, Msz/64), 256, SM_G64>>>(
        DI, DM,
        (const __half*)p_yh, DI,
        (const __half*)p_wouth, (const __half*)p_woutl, DI,
        (float*)p_feat, DM, nullptr, (const float*)p_feat, DM, 0, nullptr);

    // 9) post-LN -> fp32
    ln_kernel<<<Msz/8, 256>>>((const float*)p_feat, post_g, post_b,
        (float*)p_hn, nullptr, 0);

    // 10) fused mean-pool + classifier
    poolfine_kernel<<<Bsz, 256>>>(fine_w, fine_b, out);

    (void)in_sizes; (void)n_in; (void)out_size;
}

// round 14
// speedup vs baseline: 1.1290x; 1.1290x over previous
#include <cuda_runtime.h>
#include <cuda_fp16.h>
#include <cstdint>

// ---------------- problem constants ----------------
#define Bsz 8
#define Tsz 1024
#define Msz (Bsz*Tsz)        // 8192
#define DM  256
#define DI  512
#define DS  16
#define NCLS 60
#define KF  256              // 225 padded to 256 (zero-filled)
#define CH  32               // scan chunk

// ---------------- device scratch ----------------
__device__ __half g_fk_h[Msz*KF];          // features fp16 (A of embed)
__device__ float  g_feat[Msz*DM];
__device__ __half g_hn_h[Msz*DM];          // A of in_proj
__device__ float  g_xz[(size_t)Msz*1024];
__device__ float  g_xmc[Msz*DI];
__device__ __half g_xm_h[Msz*DI];          // A of x_proj
__device__ float  g_dbl[Msz*48];
__device__ __half g_dt_h[Msz*16];          // dt fp16 (fused from x_proj epilogue)
__device__ __half g_y_h[Msz*DI];           // A of out_proj
__device__ float  g_pooled[Bsz*DM];        // pooled sums (atomic accumulated)
// weights fp16 hi/lo (padded)
__device__ __half g_wemb_h[DM*KF],  g_wemb_l[DM*KF];     // 256 x 256
__device__ __half g_win_h[1024*DM], g_win_l[1024*DM];    // 1024 x 256
__device__ __half g_wxp_h[64*DI],   g_wxp_l[64*DI];      // 48->64 x 512
__device__ __half g_wout_h[DM*DI],  g_wout_l[DM*DI];     // 256 x 512

__device__ __forceinline__ float softplusf(float v){
    return v > 20.f ? v : log1pf(expf(v));
}
__device__ __forceinline__ float siluf(float v){
    return v / (1.f + __expf(-v));
}
__device__ __forceinline__ void splith(float v, __half& h, __half& l){
    h = __float2half_rn(v);
    l = __float2half_rn(v - __half2float(h));
}
__device__ __forceinline__ uint32_t smem_u32(const void* p){
    uint32_t a;
    asm("{ .reg .u64 t; cvta.to.shared.u64 t, %1; cvt.u32.u64 %0, t; }" : "=r"(a) : "l"(p));
    return a;
}
__device__ __forceinline__ void cp16(uint32_t dst, const void* src){
    asm volatile("cp.async.cg.shared.global [%0], [%1], 16;" :: "r"(dst), "l"(src));
}
__device__ __forceinline__ void mma16816(float* d, const uint32_t* a, const uint32_t* b){
    asm volatile(
        "mma.sync.aligned.m16n8k16.row.col.f32.f16.f16.f32 "
        "{%0,%1,%2,%3}, {%4,%5,%6,%7}, {%8,%9}, {%0,%1,%2,%3};"
        : "+f"(d[0]), "+f"(d[1]), "+f"(d[2]), "+f"(d[3])
        : "r"(a[0]), "r"(a[1]), "r"(a[2]), "r"(a[3]), "r"(b[0]), "r"(b[1]));
}
__device__ __forceinline__ void ldsm4(uint32_t* r, uint32_t addr){
    asm volatile("ldmatrix.sync.aligned.m8n8.x4.shared.b16 {%0,%1,%2,%3}, [%4];"
        : "=r"(r[0]), "=r"(r[1]), "=r"(r[2]), "=r"(r[3]) : "r"(addr));
}
__device__ __forceinline__ void ldsm2(uint32_t* r, uint32_t addr){
    asm volatile("ldmatrix.sync.aligned.m8n8.x2.shared.b16 {%0,%1}, [%2];"
        : "=r"(r[0]), "=r"(r[1]) : "r"(addr));
}

// ---------------- merged prep: weight splits + features + pooled zero ----------------
// grid = 2721 x 256
__global__ void prep_kernel(const float* __restrict__ x,
                            const float* __restrict__ embed_w,
                            const float* __restrict__ in_proj_w,
                            const float* __restrict__ x_proj_w,
                            const float* __restrict__ out_proj_w){
    const int b = blockIdx.x;
    const int t = threadIdx.x;
    if (b < 256){                               // embed_w: 256 x 225 -> 256 x 256 hi/lo
        int i = b*256 + t;
        int n = i >> 8, k = i & 255;
        float v = (k < 225) ? embed_w[n*225 + k] : 0.f;
        __half h, l; splith(v, h, l);
        g_wemb_h[i] = h; g_wemb_l[i] = l;
    } else if (b < 1280){                       // in_proj_w: 1024 x 256
        int i = (b-256)*256 + t;
        __half h, l; splith(in_proj_w[i], h, l);
        g_win_h[i] = h; g_win_l[i] = l;
    } else if (b < 1408){                       // x_proj_w: 48 x 512 -> 64 x 512
        int i = (b-1280)*256 + t;
        int n = i >> 9;
        float v = (n < 48) ? x_proj_w[i] : 0.f;
        __half h, l; splith(v, h, l);
        g_wxp_h[i] = h; g_wxp_l[i] = l;
    } else if (b < 1920){                       // out_proj_w: 256 x 512
        int i = (b-1408)*256 + t;
        __half h, l; splith(out_proj_w[i], h, l);
        g_wout_h[i] = h; g_wout_l[i] = l;
    } else if (b < 2720){                       // features: Msz*25 items
        int i = (b-1920)*256 + t;
        if (i >= Msz*25) return;
        int j = i % 25;
        int m = i / 25;
        int tt = m & (Tsz-1);
        const float* xr  = x + (size_t)m*75;
        const float* xr1 = xr - 75;
        const float* xr2 = xr - 150;
        size_t ob = (size_t)m*KF + j*9;
        #pragma unroll
        for (int c = 0; c < 3; c++){
            float p0 = xr[j*3+c]  - xr[c];
            float p1 = (tt>=1) ? (xr1[j*3+c] - xr1[c]) : 0.f;
            float p2 = (tt>=2) ? (xr2[j*3+c] - xr2[c]) : 0.f;
            float vel   = (tt>=1) ? (p0 - p1) : 0.f;
            float velm1 = (tt>=2) ? (p1 - p2) : 0.f;
            float acc   = (tt>=1) ? (vel - velm1) : 0.f;
            g_fk_h[ob+c]   = __float2half_rn(p0);
            g_fk_h[ob+3+c] = __float2half_rn(vel);
            g_fk_h[ob+6+c] = __float2half_rn(acc);
        }
        if (j == 0){
            __half z = __float2half_rn(0.f);
            for (int k = 225; k < KF; k++) g_fk_h[(size_t)m*KF + k] = z;
        }
    } else {                                    // zero pooled accumulator
        #pragma unroll
        for (int k = 0; k < 8; k++) g_pooled[t*8 + k] = 0.f;
    }
}

// ---------------- fp16 2-pass tensor-core GEMM (NT): C = A @ W^T (R12 proven config) ----------------
template<int MT, int NT, int KC>
__global__ __launch_bounds__(256) void gemm_h(
    int K, int N,
    const __half* __restrict__ A_, int lda,
    const __half* __restrict__ Wh_, const __half* __restrict__ Wl_, int ldw,
    float* __restrict__ C, int ldc,
    const float* __restrict__ bias,
    const float* __restrict__ addC, int ldadd,
    int act, __half* __restrict__ dtout)
{
    extern __shared__ char smem[];
    constexpr int LDT = KC + 8;                   // fp16 elems per padded row
    constexpr int SBUF = (MT + 2*NT)*LDT;         // elems per buffer
    constexpr int C8 = KC/8;                      // 16B chunks per row
    constexpr int MW = MT/32;                     // 16-row m-tiles per warp
    const uint32_t sb = smem_u32(smem);
    const int tid = threadIdx.x, lane = tid & 31, warp = tid >> 5;
    const int bm = blockIdx.y * MT;
    const int bn = blockIdx.x * NT;
    const int nv = min(NT, N - bn);
    const int wm = (warp & 1) * (MT/2);
    const int wn = (warp >> 1) * (NT/4);

    float acc[MW][2][4];
    #pragma unroll
    for (int mt = 0; mt < MW; mt++)
        #pragma unroll
        for (int nt = 0; nt < 2; nt++)
            #pragma unroll
            for (int i = 0; i < 4; i++) acc[mt][nt][i] = 0.f;

    const int a_row  = wm + (lane & 15);
    const int a_colb = (lane >> 4) * 8;
    const int b_row  = wn + (lane & 7);
    const int b_colb = ((lane >> 3) & 1) * 8;

    const int NC = K / KC;

    auto load_chunk = [&](int c, int bf){
        uint32_t base = sb + (uint32_t)(bf * SBUF * 2);
        const size_t koff = (size_t)c * KC;
        #pragma unroll 2
        for (int idx = tid; idx < MT*C8; idx += 256){
            int row = idx / C8, c8 = idx - row*C8;
            cp16(base + (uint32_t)((row*LDT + c8*8) * 2),
                 A_ + (size_t)(bm + row)*lda + koff + c8*8);
        }
        #pragma unroll 2
        for (int idx = tid; idx < NT*C8; idx += 256){
            int row = idx / C8, c8 = idx - row*C8;
            uint32_t d = base + (uint32_t)(((MT + row)*LDT + c8*8) * 2);
            size_t s = (size_t)(bn + row)*ldw + koff + c8*8;
            cp16(d,              Wh_ + s);
            cp16(d + NT*LDT*2,   Wl_ + s);
        }
    };

    int buf = 0;
    load_chunk(0, 0);
    asm volatile("cp.async.commit_group;" ::: "memory");
    for (int c = 0; c < NC; c++){
        if (c + 1 < NC) load_chunk(c + 1, buf ^ 1);
        asm volatile("cp.async.commit_group;" ::: "memory");
        if (c + 1 < NC) asm volatile("cp.async.wait_group 1;" ::: "memory");
        else            asm volatile("cp.async.wait_group 0;" ::: "memory");
        __syncthreads();

        uint32_t abase = sb + (uint32_t)(buf * SBUF * 2);
        #pragma unroll
        for (int kk = 0; kk < KC; kk += 16){
            uint32_t a[MW][4];
            #pragma unroll
            for (int mt = 0; mt < MW; mt++)
                ldsm4(a[mt], abase + (uint32_t)(((a_row + mt*16)*LDT + kk + a_colb) * 2));
            uint32_t bh[2][2], bl[2][2];
            #pragma unroll
            for (int nt = 0; nt < 2; nt++){
                uint32_t bd = abase + (uint32_t)(((MT + b_row + nt*8)*LDT + kk + b_colb) * 2);
                ldsm2(bh[nt], bd);
                ldsm2(bl[nt], bd + NT*LDT*2);
            }
            #pragma unroll
            for (int mt = 0; mt < MW; mt++)
                #pragma unroll
                for (int nt = 0; nt < 2; nt++){
                    mma16816(acc[mt][nt], a[mt], bh[nt]);
                    mma16816(acc[mt][nt], a[mt], bl[nt]);
                }
        }
        __syncthreads();
        buf ^= 1;
    }

    // epilogue: fragment -> global, fused bias / softplus / residual / dt-split
    #pragma unroll
    for (int mt = 0; mt < MW; mt++){
        #pragma unroll
        for (int i = 0; i < 4; i++){
            int m = bm + wm + mt*16 + (lane >> 2) + (i >> 1)*8;
            #pragma unroll
            for (int nt = 0; nt < 2; nt++){
                int n = wn + nt*8 + (lane & 3)*2 + (i & 1);
                if (n < nv){
                    int gn = bn + n;
                    float v = acc[mt][nt][i];
                    if (bias) v += bias[gn];
                    if (act)  v  = softplusf(v);
                    if (addC) v += addC[(size_t)m*ldadd + gn];
                    C[(size_t)m*ldc + gn] = v;
                    if (dtout && gn < 16) dtout[(size_t)m*16 + gn] = __float2half_rn(v);
                }
            }
        }
    }
}

// ---------------- pre-layernorm, warp-per-row -> fp16 out ----------------
__global__ __launch_bounds__(256) void ln_kernel(
    const float* __restrict__ in, const float* __restrict__ g,
    const float* __restrict__ bta, __half* __restrict__ oh)
{
    int row  = blockIdx.x*8 + (threadIdx.x >> 5);
    int lane = threadIdx.x & 31;
    const float* p = in + (size_t)row*DM + lane*8;
    float4 v0 = *(const float4*)p;
    float4 v1 = *(const float4*)(p + 4);
    float va[8] = {v0.x,v0.y,v0.z,v0.w,v1.x,v1.y,v1.z,v1.w};
    float s = 0.f, q = 0.f;
    #pragma unroll
    for (int i = 0; i < 8; i++){ s += va[i]; q = fmaf(va[i], va[i], q); }
    #pragma unroll
    for (int o = 16; o; o >>= 1){
        s += __shfl_xor_sync(0xffffffffu, s, o);
        q += __shfl_xor_sync(0xffffffffu, q, o);
    }
    float mu  = s * (1.f/256.f);
    float var = q * (1.f/256.f) - mu*mu;
    float inv = rsqrtf(var + 1e-5f);
    float4 g0 = *(const float4*)(g + lane*8);
    float4 g1 = *(const float4*)(g + lane*8 + 4);
    float4 b0 = *(const float4*)(bta + lane*8);
    float4 b1 = *(const float4*)(bta + lane*8 + 4);
    float ga[8] = {g0.x,g0.y,g0.z,g0.w,g1.x,g1.y,g1.z,g1.w};
    float ba[8] = {b0.x,b0.y,b0.z,b0.w,b1.x,b1.y,b1.z,b1.w};
    size_t ob = (size_t)row*DM + lane*8;
    #pragma unroll
    for (int i = 0; i < 8; i++)
        oh[ob + i] = __float2half_rn((va[i] - mu) * inv * ga[i] + ba[i]);
}

// ---------------- fused post-LN + mean-pool (atomic accumulate) ----------------
__global__ __launch_bounds__(256) void lnpool_kernel(
    const float* __restrict__ in, const float* __restrict__ g,
    const float* __restrict__ bta)
{
    __shared__ float s_ws[8][256];
    int warp = threadIdx.x >> 5;
    int lane = threadIdx.x & 31;
    int row  = blockIdx.x*8 + warp;
    int b    = blockIdx.x >> 7;              // 128 blocks per batch
    const float* p = in + (size_t)row*DM + lane*8;
    float4 v0 = *(const float4*)p;
    float4 v1 = *(const float4*)(p + 4);
    float va[8] = {v0.x,v0.y,v0.z,v0.w,v1.x,v1.y,v1.z,v1.w};
    float s = 0.f, q = 0.f;
    #pragma unroll
    for (int i = 0; i < 8; i++){ s += va[i]; q = fmaf(va[i], va[i], q); }
    #pragma unroll
    for (int o = 16; o; o >>= 1){
        s += __shfl_xor_sync(0xffffffffu, s, o);
        q += __shfl_xor_sync(0xffffffffu, q, o);
    }
    float mu  = s * (1.f/256.f);
    float var = q * (1.f/256.f) - mu*mu;
    float inv = rsqrtf(var + 1e-5f);
    float4 g0 = *(const float4*)(g + lane*8);
    float4 g1 = *(const float4*)(g + lane*8 + 4);
    float4 b0 = *(const float4*)(bta + lane*8);
    float4 b1 = *(const float4*)(bta + lane*8 + 4);
    float ga[8] = {g0.x,g0.y,g0.z,g0.w,g1.x,g1.y,g1.z,g1.w};
    float ba[8] = {b0.x,b0.y,b0.z,b0.w,b1.x,b1.y,b1.z,b1.w};
    float r[8];
    #pragma unroll
    for (int i = 0; i < 8; i++) r[i] = (va[i] - mu) * inv * ga[i] + ba[i];
    *(float4*)&s_ws[warp][lane*8]     = make_float4(r[0], r[1], r[2], r[3]);
    *(float4*)&s_ws[warp][lane*8 + 4] = make_float4(r[4], r[5], r[6], r[7]);
    __syncthreads();
    int c = threadIdx.x;
    float acc = 0.f;
    #pragma unroll
    for (int w = 0; w < 8; w++) acc += s_ws[w][c];
    atomicAdd(&g_pooled[b*DM + c], acc);
}

// ---------------- causal depthwise conv (k=4) + silu (fp32 + fp16 out) ----------------
__global__ void conv_silu_kernel(const float* __restrict__ cw, const float* __restrict__ cb){
    int i = blockIdx.x*blockDim.x + threadIdx.x;
    int d = i & (DI-1);
    int m = i >> 9;
    int t = m & (Tsz-1);
    float w0 = cw[d*4+0], w1 = cw[d*4+1], w2 = cw[d*4+2], w3 = cw[d*4+3];
    float a = cb[d];
    a = fmaf(w3, g_xz[(size_t)m*1024 + d], a);
    if (t >= 1) a = fmaf(w2, g_xz[(size_t)(m-1)*1024 + d], a);
    if (t >= 2) a = fmaf(w1, g_xz[(size_t)(m-2)*1024 + d], a);
    if (t >= 3) a = fmaf(w0, g_xz[(size_t)(m-3)*1024 + d], a);
    float sv = siluf(a);
    g_xmc[i] = sv;
    g_xm_h[i] = __float2half_rn(sv);
}

// ---------------- selective scan: SHFL-free, dt_proj fused, CH=32 ----------------
__global__ __launch_bounds__(128) void scan_kernel(
    const float* __restrict__ A_log, const float* __restrict__ Dp,
    const float* __restrict__ dt_w, const float* __restrict__ dt_b)
{
    __shared__ float s_dv [2][CH][8];
    __shared__ float s_uv [2][CH][8];
    __shared__ float s_res[2][CH][8];
    __shared__ float s_bc [2][CH][32];
    __shared__ float s_p  [CH][8][17];
    __shared__ float s_wdt[8][17];
    __shared__ float s_db[8];

    const int tid  = threadIdx.x;
    const int lane = tid & 31;
    const int warp = tid >> 5;
    const int b     = blockIdx.x >> 6;
    const int dbase = (blockIdx.x & 63) * 8;
    const int dloc  = warp*2 + (lane >> 4);
    const int d     = dbase + dloc;
    const int n     = lane & 15;

    const float a  = -expf(A_log[d*DS + n]);
    const size_t base = (size_t)b * Tsz;

    const int lt = tid >> 3;
    const int ld = tid & 7;
    const int bt = tid >> 5;
    const int bcc = tid & 31;
    const float DdR = Dp[dbase + ld];

    {
        int dd = tid >> 4, kk = tid & 15;
        s_wdt[dd][kk] = dt_w[(dbase + dd)*16 + kk];
        if (tid < 8) s_db[tid] = dt_b[dbase + tid];
    }
    __syncthreads();

    auto calc_dv = [&](size_t row)->float{
        const __half2* dp = (const __half2*)(g_dt_h + row*16);
        float s = s_db[ld];
        #pragma unroll
        for (int k = 0; k < 8; k++){
            float2 v = __half22float2(dp[k]);
            s = fmaf(v.x, s_wdt[ld][2*k],   s);
            s = fmaf(v.y, s_wdt[ld][2*k+1], s);
        }
        return softplusf(s);
    };

    {
        #pragma unroll
        for (int hh = 0; hh < 2; hh++){
            int rr = lt + hh*16;
            size_t row = base + rr;
            s_dv [0][rr][ld] = calc_dv(row);
            s_uv [0][rr][ld] = g_xmc[row*DI + dbase + ld];
            s_res[0][rr][ld] = g_xz [row*1024 + 512 + dbase + ld];
        }
        #pragma unroll
        for (int r = 0; r < 8; r++)
            s_bc[0][bt + r*4][bcc] = g_dbl[(base + bt + r*4)*48 + 16 + bcc];
    }
    __syncthreads();

    float h = 0.f;
    int buf = 0;
    for (int tcb = 0; tcb < Tsz; tcb += CH){
        const bool more = (tcb + CH) < Tsz;
        float r_dv[2], r_uv[2], r_res[2], r_bc[8];
        if (more){
            #pragma unroll
            for (int hh = 0; hh < 2; hh++){
                size_t row = base + tcb + CH + lt + hh*16;
                r_dv[hh]  = calc_dv(row);
                r_uv[hh]  = g_xmc[row*DI + dbase + ld];
                r_res[hh] = g_xz [row*1024 + 512 + dbase + ld];
            }
            #pragma unroll
            for (int r = 0; r < 8; r++)
                r_bc[r] = g_dbl[(base + tcb + CH + bt + r*4)*48 + 16 + bcc];
        }
        #pragma unroll
        for (int i = 0; i < CH; i++){
            float dv = s_dv[buf][i][dloc];
            float uv = s_uv[buf][i][dloc];
            float Bn = s_bc[buf][i][n];
            float Cn = s_bc[buf][i][16 + n];
            float dA = __expf(dv * a);
            h = fmaf(dA, h, dv * Bn * uv);
            s_p[i][dloc][n] = h * Cn;
        }
        __syncthreads();
        #pragma unroll
        for (int hh = 0; hh < 2; hh++){
            int rr = lt + hh*16;
            float s = 0.f;
            #pragma unroll
            for (int k = 0; k < 16; k++) s += s_p[rr][ld][k];
            float uv = s_uv[buf][rr][ld];
            float rv = s_res[buf][rr][ld];
            float yv = fmaf(uv, DdR, s) * siluf(rv);
            g_y_h[(base + tcb + rr)*DI + dbase + ld] = __float2half_rn(yv);
        }
        if (more){
            int nb = buf ^ 1;
            #pragma unroll
            for (int hh = 0; hh < 2; hh++){
                int rr = lt + hh*16;
                s_dv [nb][rr][ld] = r_dv[hh];
                s_uv [nb][rr][ld] = r_uv[hh];
                s_res[nb][rr][ld] = r_res[hh];
            }
            #pragma unroll
            for (int r = 0; r < 8; r++)
                s_bc[nb][bt + r*4][bcc] = r_bc[r];
        }
        __syncthreads();
        buf ^= 1;
    }
}

// ---------------- classifier head (reads pooled sums) ----------------
__global__ __launch_bounds__(256) void fine_kernel(
    const float* __restrict__ fw, const float* __restrict__ fb,
    float* __restrict__ out)
{
    int b = blockIdx.x;
    int tid = threadIdx.x;
    int nn = tid >> 2;
    int q  = tid & 3;
    if (nn < NCLS){
        const float* wr = fw + nn*DM + q*64;
        const float* pr = g_pooled + b*DM + q*64;
        float s = 0.f;
        #pragma unroll
        for (int k = 0; k < 64; k++) s = fmaf(pr[k], wr[k], s);
        s += __shfl_xor_sync(0xffffffffu, s, 1);
        s += __shfl_xor_sync(0xffffffffu, s, 2);
        if (q == 0) out[b*NCLS + nn] = s * (1.f/1024.f) + fb[nn];
    }
}

// ---------------- launch ----------------
extern "C" void kernel_launch(void* const* d_in, const int* in_sizes, int n_in,
                              void* d_out, int out_size)
{
    const float* x          = (const float*)d_in[0];
    const float* embed_w    = (const float*)d_in[1];
    const float* embed_b    = (const float*)d_in[2];
    const float* pre_g      = (const float*)d_in[3];
    const float* pre_b      = (const float*)d_in[4];
    const float* in_proj_w  = (const float*)d_in[5];
    const float* conv_w     = (const float*)d_in[6];
    const float* conv_b     = (const float*)d_in[7];
    const float* x_proj_w   = (const float*)d_in[8];
    const float* dt_proj_w  = (const float*)d_in[9];
    const float* dt_proj_b  = (const float*)d_in[10];
    const float* A_log      = (const float*)d_in[11];
    const float* Dp         = (const float*)d_in[12];
    const float* out_proj_w = (const float*)d_in[13];
    const float* post_g     = (const float*)d_in[14];
    const float* post_b     = (const float*)d_in[15];
    const float* fine_w     = (const float*)d_in[16];
    const float* fine_b     = (const float*)d_in[17];
    float* out = (float*)d_out;

    void *p_fk,*p_feat,*p_hnh,*p_xz,*p_xmh,*p_dbl,*p_dth,*p_yh,
         *p_wembh,*p_wembl,*p_winh,*p_winl,*p_wxph,*p_wxpl,*p_wouth,*p_woutl;
    cudaGetSymbolAddress(&p_fk, g_fk_h);
    cudaGetSymbolAddress(&p_feat, g_feat);
    cudaGetSymbolAddress(&p_hnh, g_hn_h);
    cudaGetSymbolAddress(&p_xz, g_xz);       cudaGetSymbolAddress(&p_xmh, g_xm_h);
    cudaGetSymbolAddress(&p_dbl, g_dbl);     cudaGetSymbolAddress(&p_dth, g_dt_h);
    cudaGetSymbolAddress(&p_yh, g_y_h);
    cudaGetSymbolAddress(&p_wembh, g_wemb_h); cudaGetSymbolAddress(&p_wembl, g_wemb_l);
    cudaGetSymbolAddress(&p_winh, g_win_h);   cudaGetSymbolAddress(&p_winl, g_win_l);
    cudaGetSymbolAddress(&p_wxph, g_wxp_h);   cudaGetSymbolAddress(&p_wxpl, g_wxp_l);
    cudaGetSymbolAddress(&p_wouth, g_wout_h); cudaGetSymbolAddress(&p_woutl, g_wout_l);

    const int SM_G128 = 2 * ((128 + 128)*(64+8)) * 2;  // 73728 B
    const int SM_G64  = 2 * ((64  + 128)*(64+8)) * 2;  // 55296 B
    cudaFuncSetAttribute(gemm_h<128,64,64>, cudaFuncAttributeMaxDynamicSharedMemorySize, SM_G128);
    cudaFuncSetAttribute(gemm_h<64,64,64>,  cudaFuncAttributeMaxDynamicSharedMemorySize, SM_G64);

    // 1) merged prep (weight splits + features + pooled zero)
    prep_kernel<<<2721, 256>>>(x, embed_w, in_proj_w, x_proj_w, out_proj_w);

    // 2) embed GEMM (MT=64: 512 CTAs)
    gemm_h<64,64,64><<<dim3(DM/64, Msz/64), 256, SM_G64>>>(
        KF, DM,
        (const __half*)p_fk, KF,
        (const __half*)p_wembh, (const __half*)p_wembl, KF,
        (float*)p_feat, DM, embed_b, nullptr, 0, 0, nullptr);

    // 3) pre-LN -> fp16
    ln_kernel<<<Msz/8, 256>>>((const float*)p_feat, pre_g, pre_b, (__half*)p_hnh);

    // 4) in_proj GEMM (MT=128, KC=64; ncu capture slot)
    gemm_h<128,64,64><<<dim3(1024/64, Msz/128), 256, SM_G128>>>(
        DM, 1024,
        (const __half*)p_hnh, DM,
        (const __half*)p_winh, (const __half*)p_winl, DM,
        (float*)p_xz, 1024, nullptr, nullptr, 0, 0, nullptr);

    // 5) depthwise conv + silu
    conv_silu_kernel<<<(Msz*DI)/256, 256>>>(conv_w, conv_b);

    // 6) x_proj GEMM (N=48, dt fused; MT=64: 128 CTAs)
    gemm_h<64,64,64><<<dim3(1, Msz/64), 256, SM_G64>>>(
        DI, 48,
        (const __half*)p_xmh, DI,
        (const __half*)p_wxph, (const __half*)p_wxpl, DI,
        (float*)p_dbl, 48, nullptr, nullptr, 0, 0, (__half*)p_dth);

    // 7) selective scan (dt_proj + softplus + gate fused, SHFL-free, CH=32)
    scan_kernel<<<Bsz*64, 128>>>(A_log, Dp, dt_proj_w, dt_proj_b);

    // 8) out_proj GEMM + residual (MT=64: 512 CTAs)
    gemm_h<64,64,64><<<dim3(DM/64, Msz/64), 256, SM_G64>>>(
        DI, DM,
        (const __half*)p_yh, DI,
        (const __half*)p_wouth, (const __half*)p_woutl, DI,
        (float*)p_feat, DM, nullptr, (const float*)p_feat, DM, 0, nullptr);

    // 9) fused post-LN + mean-pool (atomic accumulate into g_pooled)
    lnpool_kernel<<<Msz/8, 256>>>((const float*)p_feat, post_g, post_b);

    // 10) classifier
    fine_kernel<<<Bsz, 256>>>(fine_w, fine_b, out);

    (void)in_sizes; (void)n_in; (void)out_size;
}

// round 15
// speedup vs baseline: 1.1497x; 1.0183x over previous
#include <cuda_runtime.h>
#include <cuda_fp16.h>
#include <cstdint>

// ---------------- problem constants ----------------
#define Bsz 8
#define Tsz 1024
#define Msz (Bsz*Tsz)        // 8192
#define DM  256
#define DI  512
#define DS  16
#define NCLS 60
#define KF  256              // 225 padded to 256 (zero-filled)
#define CH  32               // scan chunk

// ---------------- device scratch ----------------
__device__ __half g_fk_h[Msz*KF];          // features fp16 (A of embed)
__device__ float  g_feat[Msz*DM];
__device__ __half g_hn_h[Msz*DM];          // A of in_proj
__device__ float  g_xz[(size_t)Msz*1024];
__device__ float  g_xmc[Msz*DI];
__device__ __half g_xm_h[Msz*DI];          // A of x_proj
__device__ float  g_dbl[Msz*48];           // x_proj out (split-K atomic accumulated)
__device__ __half g_y_h[Msz*DI];           // A of out_proj
__device__ float  g_pooled[Bsz*DM];        // pooled sums (atomic accumulated)
// weights fp16 hi/lo (padded)
__device__ __half g_wemb_h[DM*KF],  g_wemb_l[DM*KF];     // 256 x 256
__device__ __half g_win_h[1024*DM], g_win_l[1024*DM];    // 1024 x 256
__device__ __half g_wxp_h[64*DI],   g_wxp_l[64*DI];      // 48->64 x 512
__device__ __half g_wout_h[DM*DI],  g_wout_l[DM*DI];     // 256 x 512

__device__ __forceinline__ float softplusf(float v){
    return v > 20.f ? v : log1pf(expf(v));
}
__device__ __forceinline__ float siluf(float v){
    return v / (1.f + __expf(-v));
}
__device__ __forceinline__ void splith(float v, __half& h, __half& l){
    h = __float2half_rn(v);
    l = __float2half_rn(v - __half2float(h));
}
__device__ __forceinline__ uint32_t smem_u32(const void* p){
    uint32_t a;
    asm("{ .reg .u64 t; cvta.to.shared.u64 t, %1; cvt.u32.u64 %0, t; }" : "=r"(a) : "l"(p));
    return a;
}
__device__ __forceinline__ void cp16(uint32_t dst, const void* src){
    asm volatile("cp.async.cg.shared.global [%0], [%1], 16;" :: "r"(dst), "l"(src));
}
__device__ __forceinline__ void mma16816(float* d, const uint32_t* a, const uint32_t* b){
    asm volatile(
        "mma.sync.aligned.m16n8k16.row.col.f32.f16.f16.f32 "
        "{%0,%1,%2,%3}, {%4,%5,%6,%7}, {%8,%9}, {%0,%1,%2,%3};"
        : "+f"(d[0]), "+f"(d[1]), "+f"(d[2]), "+f"(d[3])
        : "r"(a[0]), "r"(a[1]), "r"(a[2]), "r"(a[3]), "r"(b[0]), "r"(b[1]));
}
__device__ __forceinline__ void ldsm4(uint32_t* r, uint32_t addr){
    asm volatile("ldmatrix.sync.aligned.m8n8.x4.shared.b16 {%0,%1,%2,%3}, [%4];"
        : "=r"(r[0]), "=r"(r[1]), "=r"(r[2]), "=r"(r[3]) : "r"(addr));
}
__device__ __forceinline__ void ldsm2(uint32_t* r, uint32_t addr){
    asm volatile("ldmatrix.sync.aligned.m8n8.x2.shared.b16 {%0,%1}, [%2];"
        : "=r"(r[0]), "=r"(r[1]) : "r"(addr));
}

// ---------------- merged prep: weight splits + features + zero fills ----------------
// grid = 3105 x 256
__global__ void prep_kernel(const float* __restrict__ x,
                            const float* __restrict__ embed_w,
                            const float* __restrict__ in_proj_w,
                            const float* __restrict__ x_proj_w,
                            const float* __restrict__ out_proj_w){
    const int b = blockIdx.x;
    const int t = threadIdx.x;
    if (b < 256){                               // embed_w: 256 x 225 -> 256 x 256 hi/lo
        int i = b*256 + t;
        int n = i >> 8, k = i & 255;
        float v = (k < 225) ? embed_w[n*225 + k] : 0.f;
        __half h, l; splith(v, h, l);
        g_wemb_h[i] = h; g_wemb_l[i] = l;
    } else if (b < 1280){                       // in_proj_w: 1024 x 256
        int i = (b-256)*256 + t;
        __half h, l; splith(in_proj_w[i], h, l);
        g_win_h[i] = h; g_win_l[i] = l;
    } else if (b < 1408){                       // x_proj_w: 48 x 512 -> 64 x 512
        int i = (b-1280)*256 + t;
        int n = i >> 9;
        float v = (n < 48) ? x_proj_w[i] : 0.f;
        __half h, l; splith(v, h, l);
        g_wxp_h[i] = h; g_wxp_l[i] = l;
    } else if (b < 1920){                       // out_proj_w: 256 x 512
        int i = (b-1408)*256 + t;
        __half h, l; splith(out_proj_w[i], h, l);
        g_wout_h[i] = h; g_wout_l[i] = l;
    } else if (b < 2720){                       // features: Msz*25 items
        int i = (b-1920)*256 + t;
        if (i >= Msz*25) return;
        int j = i % 25;
        int m = i / 25;
        int tt = m & (Tsz-1);
        const float* xr  = x + (size_t)m*75;
        const float* xr1 = xr - 75;
        const float* xr2 = xr - 150;
        size_t ob = (size_t)m*KF + j*9;
        #pragma unroll
        for (int c = 0; c < 3; c++){
            float p0 = xr[j*3+c]  - xr[c];
            float p1 = (tt>=1) ? (xr1[j*3+c] - xr1[c]) : 0.f;
            float p2 = (tt>=2) ? (xr2[j*3+c] - xr2[c]) : 0.f;
            float vel   = (tt>=1) ? (p0 - p1) : 0.f;
            float velm1 = (tt>=2) ? (p1 - p2) : 0.f;
            float acc   = (tt>=1) ? (vel - velm1) : 0.f;
            g_fk_h[ob+c]   = __float2half_rn(p0);
            g_fk_h[ob+3+c] = __float2half_rn(vel);
            g_fk_h[ob+6+c] = __float2half_rn(acc);
        }
        if (j == 0){
            __half z = __float2half_rn(0.f);
            for (int k = 225; k < KF; k++) g_fk_h[(size_t)m*KF + k] = z;
        }
    } else if (b == 2720){                      // zero pooled accumulator
        #pragma unroll
        for (int k = 0; k < 8; k++) g_pooled[t*8 + k] = 0.f;
    } else {                                    // zero g_dbl (split-K accumulator): 384 blocks
        int i = (b-2721)*256 + t;               // float4 index, 384*256*4 = Msz*48
        ((float4*)g_dbl)[i] = make_float4(0.f,0.f,0.f,0.f);
    }
}

// ---------------- fp16 2-pass tensor-core GEMM (NT): C = A @ W^T ----------------
// Tile MT x NT, block 256 thr (8 warps, 2M x 4N). KC=64 proven config.
// nkspl > 1: blockIdx.z selects K-slice (K = per-slice size); epilogue atomicAdd.
template<int MT, int NT, int KC>
__global__ __launch_bounds__(256) void gemm_h(
    int K, int N,
    const __half* __restrict__ A_, int lda,
    const __half* __restrict__ Wh_, const __half* __restrict__ Wl_, int ldw,
    float* __restrict__ C, int ldc,
    const float* __restrict__ bias,
    const float* __restrict__ addC, int ldadd,
    int act, int nkspl)
{
    extern __shared__ char smem[];
    constexpr int LDT = KC + 8;                   // fp16 elems per padded row
    constexpr int SBUF = (MT + 2*NT)*LDT;         // elems per buffer
    constexpr int C8 = KC/8;                      // 16B chunks per row
    constexpr int MW = MT/32;                     // 16-row m-tiles per warp
    const uint32_t sb = smem_u32(smem);
    const int tid = threadIdx.x, lane = tid & 31, warp = tid >> 5;
    const int bm = blockIdx.y * MT;
    const int bn = blockIdx.x * NT;
    const int nv = min(NT, N - bn);
    const int wm = (warp & 1) * (MT/2);
    const int wn = (warp >> 1) * (NT/4);

    if (nkspl > 1){
        size_t kb = (size_t)blockIdx.z * K;
        A_ += kb; Wh_ += kb; Wl_ += kb;
    }

    float acc[MW][2][4];
    #pragma unroll
    for (int mt = 0; mt < MW; mt++)
        #pragma unroll
        for (int nt = 0; nt < 2; nt++)
            #pragma unroll
            for (int i = 0; i < 4; i++) acc[mt][nt][i] = 0.f;

    const int a_row  = wm + (lane & 15);
    const int a_colb = (lane >> 4) * 8;
    const int b_row  = wn + (lane & 7);
    const int b_colb = ((lane >> 3) & 1) * 8;

    const int NC = K / KC;

    auto load_chunk = [&](int c, int bf){
        uint32_t base = sb + (uint32_t)(bf * SBUF * 2);
        const size_t koff = (size_t)c * KC;
        #pragma unroll 2
        for (int idx = tid; idx < MT*C8; idx += 256){
            int row = idx / C8, c8 = idx - row*C8;
            cp16(base + (uint32_t)((row*LDT + c8*8) * 2),
                 A_ + (size_t)(bm + row)*lda + koff + c8*8);
        }
        #pragma unroll 2
        for (int idx = tid; idx < NT*C8; idx += 256){
            int row = idx / C8, c8 = idx - row*C8;
            uint32_t d = base + (uint32_t)(((MT + row)*LDT + c8*8) * 2);
            size_t s = (size_t)(bn + row)*ldw + koff + c8*8;
            cp16(d,              Wh_ + s);
            cp16(d + NT*LDT*2,   Wl_ + s);
        }
    };

    int buf = 0;
    load_chunk(0, 0);
    asm volatile("cp.async.commit_group;" ::: "memory");
    for (int c = 0; c < NC; c++){
        if (c + 1 < NC) load_chunk(c + 1, buf ^ 1);
        asm volatile("cp.async.commit_group;" ::: "memory");
        if (c + 1 < NC) asm volatile("cp.async.wait_group 1;" ::: "memory");
        else            asm volatile("cp.async.wait_group 0;" ::: "memory");
        __syncthreads();

        uint32_t abase = sb + (uint32_t)(buf * SBUF * 2);
        #pragma unroll
        for (int kk = 0; kk < KC; kk += 16){
            uint32_t a[MW][4];
            #pragma unroll
            for (int mt = 0; mt < MW; mt++)
                ldsm4(a[mt], abase + (uint32_t)(((a_row + mt*16)*LDT + kk + a_colb) * 2));
            uint32_t bh[2][2], bl[2][2];
            #pragma unroll
            for (int nt = 0; nt < 2; nt++){
                uint32_t bd = abase + (uint32_t)(((MT + b_row + nt*8)*LDT + kk + b_colb) * 2);
                ldsm2(bh[nt], bd);
                ldsm2(bl[nt], bd + NT*LDT*2);
            }
            #pragma unroll
            for (int mt = 0; mt < MW; mt++)
                #pragma unroll
                for (int nt = 0; nt < 2; nt++){
                    mma16816(acc[mt][nt], a[mt], bh[nt]);
                    mma16816(acc[mt][nt], a[mt], bl[nt]);
                }
        }
        __syncthreads();
        buf ^= 1;
    }

    // epilogue
    #pragma unroll
    for (int mt = 0; mt < MW; mt++){
        #pragma unroll
        for (int i = 0; i < 4; i++){
            int m = bm + wm + mt*16 + (lane >> 2) + (i >> 1)*8;
            #pragma unroll
            for (int nt = 0; nt < 2; nt++){
                int n = wn + nt*8 + (lane & 3)*2 + (i & 1);
                if (n < nv){
                    int gn = bn + n;
                    float v = acc[mt][nt][i];
                    if (nkspl > 1){
                        atomicAdd(&C[(size_t)m*ldc + gn], v);
                    } else {
                        if (bias) v += bias[gn];
                        if (act)  v  = softplusf(v);
                        if (addC) v += addC[(size_t)m*ldadd + gn];
                        C[(size_t)m*ldc + gn] = v;
                    }
                }
            }
        }
    }
}

// ---------------- pre-layernorm, warp-per-row -> fp16 out ----------------
__global__ __launch_bounds__(256) void ln_kernel(
    const float* __restrict__ in, const float* __restrict__ g,
    const float* __restrict__ bta, __half* __restrict__ oh)
{
    int row  = blockIdx.x*8 + (threadIdx.x >> 5);
    int lane = threadIdx.x & 31;
    const float* p = in + (size_t)row*DM + lane*8;
    float4 v0 = *(const float4*)p;
    float4 v1 = *(const float4*)(p + 4);
    float va[8] = {v0.x,v0.y,v0.z,v0.w,v1.x,v1.y,v1.z,v1.w};
    float s = 0.f, q = 0.f;
    #pragma unroll
    for (int i = 0; i < 8; i++){ s += va[i]; q = fmaf(va[i], va[i], q); }
    #pragma unroll
    for (int o = 16; o; o >>= 1){
        s += __shfl_xor_sync(0xffffffffu, s, o);
        q += __shfl_xor_sync(0xffffffffu, q, o);
    }
    float mu  = s * (1.f/256.f);
    float var = q * (1.f/256.f) - mu*mu;
    float inv = rsqrtf(var + 1e-5f);
    float4 g0 = *(const float4*)(g + lane*8);
    float4 g1 = *(const float4*)(g + lane*8 + 4);
    float4 b0 = *(const float4*)(bta + lane*8);
    float4 b1 = *(const float4*)(bta + lane*8 + 4);
    float ga[8] = {g0.x,g0.y,g0.z,g0.w,g1.x,g1.y,g1.z,g1.w};
    float ba[8] = {b0.x,b0.y,b0.z,b0.w,b1.x,b1.y,b1.z,b1.w};
    size_t ob = (size_t)row*DM + lane*8;
    #pragma unroll
    for (int i = 0; i < 8; i++)
        oh[ob + i] = __float2half_rn((va[i] - mu) * inv * ga[i] + ba[i]);
}

// ---------------- fused post-LN + mean-pool (atomic accumulate) ----------------
__global__ __launch_bounds__(256) void lnpool_kernel(
    const float* __restrict__ in, const float* __restrict__ g,
    const float* __restrict__ bta)
{
    __shared__ float s_ws[8][256];
    int warp = threadIdx.x >> 5;
    int lane = threadIdx.x & 31;
    int row  = blockIdx.x*8 + warp;
    int b    = blockIdx.x >> 7;
    const float* p = in + (size_t)row*DM + lane*8;
    float4 v0 = *(const float4*)p;
    float4 v1 = *(const float4*)(p + 4);
    float va[8] = {v0.x,v0.y,v0.z,v0.w,v1.x,v1.y,v1.z,v1.w};
    float s = 0.f, q = 0.f;
    #pragma unroll
    for (int i = 0; i < 8; i++){ s += va[i]; q = fmaf(va[i], va[i], q); }
    #pragma unroll
    for (int o = 16; o; o >>= 1){
        s += __shfl_xor_sync(0xffffffffu, s, o);
        q += __shfl_xor_sync(0xffffffffu, q, o);
    }
    float mu  = s * (1.f/256.f);
    float var = q * (1.f/256.f) - mu*mu;
    float inv = rsqrtf(var + 1e-5f);
    float4 g0 = *(const float4*)(g + lane*8);
    float4 g1 = *(const float4*)(g + lane*8 + 4);
    float4 b0 = *(const float4*)(bta + lane*8);
    float4 b1 = *(const float4*)(bta + lane*8 + 4);
    float ga[8] = {g0.x,g0.y,g0.z,g0.w,g1.x,g1.y,g1.z,g1.w};
    float ba[8] = {b0.x,b0.y,b0.z,b0.w,b1.x,b1.y,b1.z,b1.w};
    float r[8];
    #pragma unroll
    for (int i = 0; i < 8; i++) r[i] = (va[i] - mu) * inv * ga[i] + ba[i];
    *(float4*)&s_ws[warp][lane*8]     = make_float4(r[0], r[1], r[2], r[3]);
    *(float4*)&s_ws[warp][lane*8 + 4] = make_float4(r[4], r[5], r[6], r[7]);
    __syncthreads();
    int c = threadIdx.x;
    float acc = 0.f;
    #pragma unroll
    for (int w = 0; w < 8; w++) acc += s_ws[w][c];
    atomicAdd(&g_pooled[b*DM + c], acc);
}

// ---------------- causal depthwise conv (k=4) + silu, 4 timesteps/thread ----------------
// grid = Msz*DI/(4*256) = 4096 blocks; thread owns (t0..t0+3, d), t0 = 4-aligned.
__global__ void conv_silu_kernel(const float* __restrict__ cw, const float* __restrict__ cb){
    int i = blockIdx.x*256 + threadIdx.x;
    int d  = i & (DI-1);
    int g4 = i >> 9;                 // 0..2047
    int m0 = g4 * 4;                 // first global row
    int t0 = m0 & (Tsz-1);
    float w0 = cw[d*4+0], w1 = cw[d*4+1], w2 = cw[d*4+2], w3 = cw[d*4+3];
    float bias = cb[d];
    float xv[7];
    const float* src = g_xz + (size_t)m0*1024 + d;
    xv[0] = (t0 >= 3) ? src[-3*1024] : 0.f;
    xv[1] = (t0 >= 2) ? src[-2*1024] : 0.f;
    xv[2] = (t0 >= 1) ? src[-1*1024] : 0.f;
    #pragma unroll
    for (int j = 0; j < 4; j++) xv[3+j] = src[j*1024];
    #pragma unroll
    for (int k = 0; k < 4; k++){
        float a = bias;
        a = fmaf(w0, xv[k],   a);
        a = fmaf(w1, xv[k+1], a);
        a = fmaf(w2, xv[k+2], a);
        a = fmaf(w3, xv[k+3], a);
        float sv = siluf(a);
        size_t o = (size_t)(m0+k)*DI + d;
        g_xmc[o]  = sv;
        g_xm_h[o] = __float2half_rn(sv);
    }
}

// ---------------- selective scan: SHFL-free, dt_proj fused (fp32 dt from g_dbl), CH=32 ----------------
__global__ __launch_bounds__(128) void scan_kernel(
    const float* __restrict__ A_log, const float* __restrict__ Dp,
    const float* __restrict__ dt_w, const float* __restrict__ dt_b)
{
    __shared__ float s_dv [2][CH][8];
    __shared__ float s_uv [2][CH][8];
    __shared__ float s_res[2][CH][8];
    __shared__ float s_bc [2][CH][32];
    __shared__ float s_p  [CH][8][17];
    __shared__ float s_wdt[8][17];
    __shared__ float s_db[8];

    const int tid  = threadIdx.x;
    const int lane = tid & 31;
    const int warp = tid >> 5;
    const int b     = blockIdx.x >> 6;
    const int dbase = (blockIdx.x & 63) * 8;
    const int dloc  = warp*2 + (lane >> 4);
    const int d     = dbase + dloc;
    const int n     = lane & 15;

    const float a  = -expf(A_log[d*DS + n]);
    const size_t base = (size_t)b * Tsz;

    const int lt = tid >> 3;
    const int ld = tid & 7;
    const int bt = tid >> 5;
    const int bcc = tid & 31;
    const float DdR = Dp[dbase + ld];

    {
        int dd = tid >> 4, kk = tid & 15;
        s_wdt[dd][kk] = dt_w[(dbase + dd)*16 + kk];
        if (tid < 8) s_db[tid] = dt_b[dbase + tid];
    }
    __syncthreads();

    auto calc_dv = [&](size_t row)->float{
        const float4* dp = (const float4*)(g_dbl + row*48);
        float s = s_db[ld];
        #pragma unroll
        for (int k = 0; k < 4; k++){
            float4 v = dp[k];
            s = fmaf(v.x, s_wdt[ld][4*k],   s);
            s = fmaf(v.y, s_wdt[ld][4*k+1], s);
            s = fmaf(v.z, s_wdt[ld][4*k+2], s);
            s = fmaf(v.w, s_wdt[ld][4*k+3], s);
        }
        return softplusf(s);
    };

    {
        #pragma unroll
        for (int hh = 0; hh < 2; hh++){
            int rr = lt + hh*16;
            size_t row = base + rr;
            s_dv [0][rr][ld] = calc_dv(row);
            s_uv [0][rr][ld] = g_xmc[row*DI + dbase + ld];
            s_res[0][rr][ld] = g_xz [row*1024 + 512 + dbase + ld];
        }
        #pragma unroll
        for (int r = 0; r < 8; r++)
            s_bc[0][bt + r*4][bcc] = g_dbl[(base + bt + r*4)*48 + 16 + bcc];
    }
    __syncthreads();

    float h = 0.f;
    int buf = 0;
    for (int tcb = 0; tcb < Tsz; tcb += CH){
        const bool more = (tcb + CH) < Tsz;
        float r_dv[2], r_uv[2], r_res[2], r_bc[8];
        if (more){
            #pragma unroll
            for (int hh = 0; hh < 2; hh++){
                size_t row = base + tcb + CH + lt + hh*16;
                r_dv[hh]  = calc_dv(row);
                r_uv[hh]  = g_xmc[row*DI + dbase + ld];
                r_res[hh] = g_xz [row*1024 + 512 + dbase + ld];
            }
            #pragma unroll
            for (int r = 0; r < 8; r++)
                r_bc[r] = g_dbl[(base + tcb + CH + bt + r*4)*48 + 16 + bcc];
        }
        #pragma unroll
        for (int i = 0; i < CH; i++){
            float dv = s_dv[buf][i][dloc];
            float uv = s_uv[buf][i][dloc];
            float Bn = s_bc[buf][i][n];
            float Cn = s_bc[buf][i][16 + n];
            float dA = __expf(dv * a);
            h = fmaf(dA, h, dv * Bn * uv);
            s_p[i][dloc][n] = h * Cn;
        }
        __syncthreads();
        #pragma unroll
        for (int hh = 0; hh < 2; hh++){
            int rr = lt + hh*16;
            float s = 0.f;
            #pragma unroll
            for (int k = 0; k < 16; k++) s += s_p[rr][ld][k];
            float uv = s_uv[buf][rr][ld];
            float rv = s_res[buf][rr][ld];
            float yv = fmaf(uv, DdR, s) * siluf(rv);
            g_y_h[(base + tcb + rr)*DI + dbase + ld] = __float2half_rn(yv);
        }
        if (more){
            int nb = buf ^ 1;
            #pragma unroll
            for (int hh = 0; hh < 2; hh++){
                int rr = lt + hh*16;
                s_dv [nb][rr][ld] = r_dv[hh];
                s_uv [nb][rr][ld] = r_uv[hh];
                s_res[nb][rr][ld] = r_res[hh];
            }
            #pragma unroll
            for (int r = 0; r < 8; r++)
                s_bc[nb][bt + r*4][bcc] = r_bc[r];
        }
        __syncthreads();
        buf ^= 1;
    }
}

// ---------------- classifier head (reads pooled sums) ----------------
__global__ __launch_bounds__(256) void fine_kernel(
    const float* __restrict__ fw, const float* __restrict__ fb,
    float* __restrict__ out)
{
    int b = blockIdx.x;
    int tid = threadIdx.x;
    int nn = tid >> 2;
    int q  = tid & 3;
    if (nn < NCLS){
        const float* wr = fw + nn*DM + q*64;
        const float* pr = g_pooled + b*DM + q*64;
        float s = 0.f;
        #pragma unroll
        for (int k = 0; k < 64; k++) s = fmaf(pr[k], wr[k], s);
        s += __shfl_xor_sync(0xffffffffu, s, 1);
        s += __shfl_xor_sync(0xffffffffu, s, 2);
        if (q == 0) out[b*NCLS + nn] = s * (1.f/1024.f) + fb[nn];
    }
}

// ---------------- launch ----------------
extern "C" void kernel_launch(void* const* d_in, const int* in_sizes, int n_in,
                              void* d_out, int out_size)
{
    const float* x          = (const float*)d_in[0];
    const float* embed_w    = (const float*)d_in[1];
    const float* embed_b    = (const float*)d_in[2];
    const float* pre_g      = (const float*)d_in[3];
    const float* pre_b      = (const float*)d_in[4];
    const float* in_proj_w  = (const float*)d_in[5];
    const float* conv_w     = (const float*)d_in[6];
    const float* conv_b     = (const float*)d_in[7];
    const float* x_proj_w   = (const float*)d_in[8];
    const float* dt_proj_w  = (const float*)d_in[9];
    const float* dt_proj_b  = (const float*)d_in[10];
    const float* A_log      = (const float*)d_in[11];
    const float* Dp         = (const float*)d_in[12];
    const float* out_proj_w = (const float*)d_in[13];
    const float* post_g     = (const float*)d_in[14];
    const float* post_b     = (const float*)d_in[15];
    const float* fine_w     = (const float*)d_in[16];
    const float* fine_b     = (const float*)d_in[17];
    float* out = (float*)d_out;

    void *p_fk,*p_feat,*p_hnh,*p_xz,*p_xmh,*p_dbl,*p_yh,
         *p_wembh,*p_wembl,*p_winh,*p_winl,*p_wxph,*p_wxpl,*p_wouth,*p_woutl;
    cudaGetSymbolAddress(&p_fk, g_fk_h);
    cudaGetSymbolAddress(&p_feat, g_feat);
    cudaGetSymbolAddress(&p_hnh, g_hn_h);
    cudaGetSymbolAddress(&p_xz, g_xz);       cudaGetSymbolAddress(&p_xmh, g_xm_h);
    cudaGetSymbolAddress(&p_dbl, g_dbl);
    cudaGetSymbolAddress(&p_yh, g_y_h);
    cudaGetSymbolAddress(&p_wembh, g_wemb_h); cudaGetSymbolAddress(&p_wembl, g_wemb_l);
    cudaGetSymbolAddress(&p_winh, g_win_h);   cudaGetSymbolAddress(&p_winl, g_win_l);
    cudaGetSymbolAddress(&p_wxph, g_wxp_h);   cudaGetSymbolAddress(&p_wxpl, g_wxp_l);
    cudaGetSymbolAddress(&p_wouth, g_wout_h); cudaGetSymbolAddress(&p_woutl, g_wout_l);

    const int SM_G128 = 2 * ((128 + 128)*(64+8)) * 2;  // 73728 B
    const int SM_G64  = 2 * ((64  + 128)*(64+8)) * 2;  // 55296 B
    cudaFuncSetAttribute(gemm_h<128,64,64>, cudaFuncAttributeMaxDynamicSharedMemorySize, SM_G128);
    cudaFuncSetAttribute(gemm_h<64,64,64>,  cudaFuncAttributeMaxDynamicSharedMemorySize, SM_G64);

    // 1) merged prep (weight splits + features + zero fills)
    prep_kernel<<<3105, 256>>>(x, embed_w, in_proj_w, x_proj_w, out_proj_w);

    // 2) embed GEMM (MT=64: 512 CTAs)
    gemm_h<64,64,64><<<dim3(DM/64, Msz/64), 256, SM_G64>>>(
        KF, DM,
        (const __half*)p_fk, KF,
        (const __half*)p_wembh, (const __half*)p_wembl, KF,
        (float*)p_feat, DM, embed_b, nullptr, 0, 0, 1);

    // 3) pre-LN -> fp16
    ln_kernel<<<Msz/8, 256>>>((const float*)p_feat, pre_g, pre_b, (__half*)p_hnh);

    // 4) in_proj GEMM (MT=128, KC=64; ncu capture slot)
    gemm_h<128,64,64><<<dim3(1024/64, Msz/128), 256, SM_G128>>>(
        DM, 1024,
        (const __half*)p_hnh, DM,
        (const __half*)p_winh, (const __half*)p_winl, DM,
        (float*)p_xz, 1024, nullptr, nullptr, 0, 0, 1);

    // 5) depthwise conv + silu (4 timesteps/thread)
    conv_silu_kernel<<<(Msz/4)*DI/256, 256>>>(conv_w, conv_b);

    // 6) x_proj GEMM split-K=2 (atomic accumulate into zeroed g_dbl)
    gemm_h<64,64,64><<<dim3(1, Msz/64, 2), 256, SM_G64>>>(
        256, 48,
        (const __half*)p_xmh, DI,
        (const __half*)p_wxph, (const __half*)p_wxpl, DI,
        (float*)p_dbl, 48, nullptr, nullptr, 0, 0, 2);

    // 7) selective scan (dt_proj fp32 + softplus + gate fused, SHFL-free, CH=32)
    scan_kernel<<<Bsz*64, 128>>>(A_log, Dp, dt_proj_w, dt_proj_b);

    // 8) out_proj GEMM + residual (MT=64: 512 CTAs)
    gemm_h<64,64,64><<<dim3(DM/64, Msz/64), 256, SM_G64>>>(
        DI, DM,
        (const __half*)p_yh, DI,
        (const __half*)p_wouth, (const __half*)p_woutl, DI,
        (float*)p_feat, DM, nullptr, (const float*)p_feat, DM, 0, 1);

    // 9) fused post-LN + mean-pool (atomic accumulate into g_pooled)
    lnpool_kernel<<<Msz/8, 256>>>((const float*)p_feat, post_g, post_b);

    // 10) classifier
    fine_kernel<<<Bsz, 256>>>(fine_w, fine_b, out);

    (void)in_sizes; (void)n_in; (void)out_size;
}

// round 16
// speedup vs baseline: 1.2356x; 1.0747x over previous
#include <cuda_runtime.h>
#include <cuda_fp16.h>
#include <cstdint>

// ---------------- problem constants ----------------
#define Bsz 8
#define Tsz 1024
#define Msz (Bsz*Tsz)        // 8192
#define DM  256
#define DI  512
#define DS  16
#define NCLS 60
#define KF  256              // 225 padded to 256 (zero-filled)
#define CH  32               // scan chunk

// ---------------- device scratch ----------------
__device__ __half g_fk_h[Msz*KF];          // features fp16 (A of embed)
__device__ float  g_feat[Msz*DM];
__device__ __half g_hn_h[Msz*DM];          // A of in_proj
__device__ float  g_xz[(size_t)Msz*1024];
__device__ float  g_xmc[Msz*DI];
__device__ __half g_xm_h[Msz*DI];          // A of x_proj
__device__ float  g_dbl[Msz*48];           // x_proj out (split-K atomic accumulated)
__device__ __half g_y_h[Msz*DI];           // A of out_proj
__device__ float  g_pooled[Bsz*DM];        // pooled sums (atomic accumulated)
// weights fp16 hi/lo (padded)
__device__ __half g_wemb_h[DM*KF],  g_wemb_l[DM*KF];     // 256 x 256
__device__ __half g_win_h[1024*DM], g_win_l[1024*DM];    // 1024 x 256
__device__ __half g_wxp_h[64*DI],   g_wxp_l[64*DI];      // 48->64 x 512
__device__ __half g_wout_h[DM*DI],  g_wout_l[DM*DI];     // 256 x 512

__device__ __forceinline__ float softplusf(float v){
    return v > 20.f ? v : log1pf(expf(v));
}
__device__ __forceinline__ float siluf(float v){
    return v / (1.f + __expf(-v));
}
__device__ __forceinline__ void splith(float v, __half& h, __half& l){
    h = __float2half_rn(v);
    l = __float2half_rn(v - __half2float(h));
}
__device__ __forceinline__ uint32_t smem_u32(const void* p){
    uint32_t a;
    asm("{ .reg .u64 t; cvta.to.shared.u64 t, %1; cvt.u32.u64 %0, t; }" : "=r"(a) : "l"(p));
    return a;
}
__device__ __forceinline__ void cp16(uint32_t dst, const void* src){
    asm volatile("cp.async.cg.shared.global [%0], [%1], 16;" :: "r"(dst), "l"(src));
}
__device__ __forceinline__ void mma16816(float* d, const uint32_t* a, const uint32_t* b){
    asm volatile(
        "mma.sync.aligned.m16n8k16.row.col.f32.f16.f16.f32 "
        "{%0,%1,%2,%3}, {%4,%5,%6,%7}, {%8,%9}, {%0,%1,%2,%3};"
        : "+f"(d[0]), "+f"(d[1]), "+f"(d[2]), "+f"(d[3])
        : "r"(a[0]), "r"(a[1]), "r"(a[2]), "r"(a[3]), "r"(b[0]), "r"(b[1]));
}
__device__ __forceinline__ void ldsm4(uint32_t* r, uint32_t addr){
    asm volatile("ldmatrix.sync.aligned.m8n8.x4.shared.b16 {%0,%1,%2,%3}, [%4];"
        : "=r"(r[0]), "=r"(r[1]), "=r"(r[2]), "=r"(r[3]) : "r"(addr));
}
__device__ __forceinline__ void ldsm2(uint32_t* r, uint32_t addr){
    asm volatile("ldmatrix.sync.aligned.m8n8.x2.shared.b16 {%0,%1}, [%2];"
        : "=r"(r[0]), "=r"(r[1]) : "r"(addr));
}

// ---------------- merged prep: weight splits + features + zero fills ----------------
// grid = 3105 x 256
__global__ void prep_kernel(const float* __restrict__ x,
                            const float* __restrict__ embed_w,
                            const float* __restrict__ in_proj_w,
                            const float* __restrict__ x_proj_w,
                            const float* __restrict__ out_proj_w){
    const int b = blockIdx.x;
    const int t = threadIdx.x;
    if (b < 256){                               // embed_w: 256 x 225 -> 256 x 256 hi/lo
        int i = b*256 + t;
        int n = i >> 8, k = i & 255;
        float v = (k < 225) ? embed_w[n*225 + k] : 0.f;
        __half h, l; splith(v, h, l);
        g_wemb_h[i] = h; g_wemb_l[i] = l;
    } else if (b < 1280){                       // in_proj_w: 1024 x 256
        int i = (b-256)*256 + t;
        __half h, l; splith(in_proj_w[i], h, l);
        g_win_h[i] = h; g_win_l[i] = l;
    } else if (b < 1408){                       // x_proj_w: 48 x 512 -> 64 x 512
        int i = (b-1280)*256 + t;
        int n = i >> 9;
        float v = (n < 48) ? x_proj_w[i] : 0.f;
        __half h, l; splith(v, h, l);
        g_wxp_h[i] = h; g_wxp_l[i] = l;
    } else if (b < 1920){                       // out_proj_w: 256 x 512
        int i = (b-1408)*256 + t;
        __half h, l; splith(out_proj_w[i], h, l);
        g_wout_h[i] = h; g_wout_l[i] = l;
    } else if (b < 2720){                       // features: Msz*25 items
        int i = (b-1920)*256 + t;
        if (i >= Msz*25) return;
        int j = i % 25;
        int m = i / 25;
        int tt = m & (Tsz-1);
        const float* xr  = x + (size_t)m*75;
        const float* xr1 = xr - 75;
        const float* xr2 = xr - 150;
        size_t ob = (size_t)m*KF + j*9;
        #pragma unroll
        for (int c = 0; c < 3; c++){
            float p0 = xr[j*3+c]  - xr[c];
            float p1 = (tt>=1) ? (xr1[j*3+c] - xr1[c]) : 0.f;
            float p2 = (tt>=2) ? (xr2[j*3+c] - xr2[c]) : 0.f;
            float vel   = (tt>=1) ? (p0 - p1) : 0.f;
            float velm1 = (tt>=2) ? (p1 - p2) : 0.f;
            float acc   = (tt>=1) ? (vel - velm1) : 0.f;
            g_fk_h[ob+c]   = __float2half_rn(p0);
            g_fk_h[ob+3+c] = __float2half_rn(vel);
            g_fk_h[ob+6+c] = __float2half_rn(acc);
        }
        if (j == 0){
            __half z = __float2half_rn(0.f);
            for (int k = 225; k < KF; k++) g_fk_h[(size_t)m*KF + k] = z;
        }
    } else if (b == 2720){                      // zero pooled accumulator
        #pragma unroll
        for (int k = 0; k < 8; k++) g_pooled[t*8 + k] = 0.f;
    } else {                                    // zero g_dbl (split-K accumulator): 384 blocks
        int i = (b-2721)*256 + t;               // float4 index, 384*256*4 = Msz*48
        ((float4*)g_dbl)[i] = make_float4(0.f,0.f,0.f,0.f);
    }
}

// ---------------- fp16 2-pass tensor-core GEMM (NT): C = A @ W^T ----------------
// Tile MT x NT, block 256 thr (8 warps, 2M x 4N). KC=64 proven config.
// nkspl > 1: blockIdx.z selects K-slice (K = per-slice size); epilogue atomicAdd into C
// (C holds the accumulation base, e.g. zeros or the residual).
template<int MT, int NT, int KC>
__global__ __launch_bounds__(256) void gemm_h(
    int K, int N,
    const __half* __restrict__ A_, int lda,
    const __half* __restrict__ Wh_, const __half* __restrict__ Wl_, int ldw,
    float* __restrict__ C, int ldc,
    const float* __restrict__ bias,
    const float* __restrict__ addC, int ldadd,
    int act, int nkspl)
{
    extern __shared__ char smem[];
    constexpr int LDT = KC + 8;                   // fp16 elems per padded row
    constexpr int SBUF = (MT + 2*NT)*LDT;         // elems per buffer
    constexpr int C8 = KC/8;                      // 16B chunks per row
    constexpr int MW = MT/32;                     // 16-row m-tiles per warp
    const uint32_t sb = smem_u32(smem);
    const int tid = threadIdx.x, lane = tid & 31, warp = tid >> 5;
    const int bm = blockIdx.y * MT;
    const int bn = blockIdx.x * NT;
    const int nv = min(NT, N - bn);
    const int wm = (warp & 1) * (MT/2);
    const int wn = (warp >> 1) * (NT/4);

    if (nkspl > 1){
        size_t kb = (size_t)blockIdx.z * K;
        A_ += kb; Wh_ += kb; Wl_ += kb;
    }

    float acc[MW][2][4];
    #pragma unroll
    for (int mt = 0; mt < MW; mt++)
        #pragma unroll
        for (int nt = 0; nt < 2; nt++)
            #pragma unroll
            for (int i = 0; i < 4; i++) acc[mt][nt][i] = 0.f;

    const int a_row  = wm + (lane & 15);
    const int a_colb = (lane >> 4) * 8;
    const int b_row  = wn + (lane & 7);
    const int b_colb = ((lane >> 3) & 1) * 8;

    const int NC = K / KC;

    auto load_chunk = [&](int c, int bf){
        uint32_t base = sb + (uint32_t)(bf * SBUF * 2);
        const size_t koff = (size_t)c * KC;
        #pragma unroll 2
        for (int idx = tid; idx < MT*C8; idx += 256){
            int row = idx / C8, c8 = idx - row*C8;
            cp16(base + (uint32_t)((row*LDT + c8*8) * 2),
                 A_ + (size_t)(bm + row)*lda + koff + c8*8);
        }
        #pragma unroll 2
        for (int idx = tid; idx < NT*C8; idx += 256){
            int row = idx / C8, c8 = idx - row*C8;
            uint32_t d = base + (uint32_t)(((MT + row)*LDT + c8*8) * 2);
            size_t s = (size_t)(bn + row)*ldw + koff + c8*8;
            cp16(d,              Wh_ + s);
            cp16(d + NT*LDT*2,   Wl_ + s);
        }
    };

    int buf = 0;
    load_chunk(0, 0);
    asm volatile("cp.async.commit_group;" ::: "memory");
    for (int c = 0; c < NC; c++){
        if (c + 1 < NC) load_chunk(c + 1, buf ^ 1);
        asm volatile("cp.async.commit_group;" ::: "memory");
        if (c + 1 < NC) asm volatile("cp.async.wait_group 1;" ::: "memory");
        else            asm volatile("cp.async.wait_group 0;" ::: "memory");
        __syncthreads();

        uint32_t abase = sb + (uint32_t)(buf * SBUF * 2);
        #pragma unroll
        for (int kk = 0; kk < KC; kk += 16){
            uint32_t a[MW][4];
            #pragma unroll
            for (int mt = 0; mt < MW; mt++)
                ldsm4(a[mt], abase + (uint32_t)(((a_row + mt*16)*LDT + kk + a_colb) * 2));
            uint32_t bh[2][2], bl[2][2];
            #pragma unroll
            for (int nt = 0; nt < 2; nt++){
                uint32_t bd = abase + (uint32_t)(((MT + b_row + nt*8)*LDT + kk + b_colb) * 2);
                ldsm2(bh[nt], bd);
                ldsm2(bl[nt], bd + NT*LDT*2);
            }
            #pragma unroll
            for (int mt = 0; mt < MW; mt++)
                #pragma unroll
                for (int nt = 0; nt < 2; nt++){
                    mma16816(acc[mt][nt], a[mt], bh[nt]);
                    mma16816(acc[mt][nt], a[mt], bl[nt]);
                }
        }
        __syncthreads();
        buf ^= 1;
    }

    // epilogue
    #pragma unroll
    for (int mt = 0; mt < MW; mt++){
        #pragma unroll
        for (int i = 0; i < 4; i++){
            int m = bm + wm + mt*16 + (lane >> 2) + (i >> 1)*8;
            #pragma unroll
            for (int nt = 0; nt < 2; nt++){
                int n = wn + nt*8 + (lane & 3)*2 + (i & 1);
                if (n < nv){
                    int gn = bn + n;
                    float v = acc[mt][nt][i];
                    if (nkspl > 1){
                        atomicAdd(&C[(size_t)m*ldc + gn], v);
                    } else {
                        if (bias) v += bias[gn];
                        if (act)  v  = softplusf(v);
                        if (addC) v += addC[(size_t)m*ldadd + gn];
                        C[(size_t)m*ldc + gn] = v;
                    }
                }
            }
        }
    }
}

// ---------------- pre-layernorm, warp-per-row -> fp16 out ----------------
__global__ __launch_bounds__(256) void ln_kernel(
    const float* __restrict__ in, const float* __restrict__ g,
    const float* __restrict__ bta, __half* __restrict__ oh)
{
    int row  = blockIdx.x*8 + (threadIdx.x >> 5);
    int lane = threadIdx.x & 31;
    const float* p = in + (size_t)row*DM + lane*8;
    float4 v0 = *(const float4*)p;
    float4 v1 = *(const float4*)(p + 4);
    float va[8] = {v0.x,v0.y,v0.z,v0.w,v1.x,v1.y,v1.z,v1.w};
    float s = 0.f, q = 0.f;
    #pragma unroll
    for (int i = 0; i < 8; i++){ s += va[i]; q = fmaf(va[i], va[i], q); }
    #pragma unroll
    for (int o = 16; o; o >>= 1){
        s += __shfl_xor_sync(0xffffffffu, s, o);
        q += __shfl_xor_sync(0xffffffffu, q, o);
    }
    float mu  = s * (1.f/256.f);
    float var = q * (1.f/256.f) - mu*mu;
    float inv = rsqrtf(var + 1e-5f);
    float4 g0 = *(const float4*)(g + lane*8);
    float4 g1 = *(const float4*)(g + lane*8 + 4);
    float4 b0 = *(const float4*)(bta + lane*8);
    float4 b1 = *(const float4*)(bta + lane*8 + 4);
    float ga[8] = {g0.x,g0.y,g0.z,g0.w,g1.x,g1.y,g1.z,g1.w};
    float ba[8] = {b0.x,b0.y,b0.z,b0.w,b1.x,b1.y,b1.z,b1.w};
    size_t ob = (size_t)row*DM + lane*8;
    #pragma unroll
    for (int i = 0; i < 8; i++)
        oh[ob + i] = __float2half_rn((va[i] - mu) * inv * ga[i] + ba[i]);
}

// ---------------- fused post-LN + mean-pool (atomic accumulate) ----------------
__global__ __launch_bounds__(256) void lnpool_kernel(
    const float* __restrict__ in, const float* __restrict__ g,
    const float* __restrict__ bta)
{
    __shared__ float s_ws[8][256];
    int warp = threadIdx.x >> 5;
    int lane = threadIdx.x & 31;
    int row  = blockIdx.x*8 + warp;
    int b    = blockIdx.x >> 7;
    const float* p = in + (size_t)row*DM + lane*8;
    float4 v0 = *(const float4*)p;
    float4 v1 = *(const float4*)(p + 4);
    float va[8] = {v0.x,v0.y,v0.z,v0.w,v1.x,v1.y,v1.z,v1.w};
    float s = 0.f, q = 0.f;
    #pragma unroll
    for (int i = 0; i < 8; i++){ s += va[i]; q = fmaf(va[i], va[i], q); }
    #pragma unroll
    for (int o = 16; o; o >>= 1){
        s += __shfl_xor_sync(0xffffffffu, s, o);
        q += __shfl_xor_sync(0xffffffffu, q, o);
    }
    float mu  = s * (1.f/256.f);
    float var = q * (1.f/256.f) - mu*mu;
    float inv = rsqrtf(var + 1e-5f);
    float4 g0 = *(const float4*)(g + lane*8);
    float4 g1 = *(const float4*)(g + lane*8 + 4);
    float4 b0 = *(const float4*)(bta + lane*8);
    float4 b1 = *(const float4*)(bta + lane*8 + 4);
    float ga[8] = {g0.x,g0.y,g0.z,g0.w,g1.x,g1.y,g1.z,g1.w};
    float ba[8] = {b0.x,b0.y,b0.z,b0.w,b1.x,b1.y,b1.z,b1.w};
    float r[8];
    #pragma unroll
    for (int i = 0; i < 8; i++) r[i] = (va[i] - mu) * inv * ga[i] + ba[i];
    *(float4*)&s_ws[warp][lane*8]     = make_float4(r[0], r[1], r[2], r[3]);
    *(float4*)&s_ws[warp][lane*8 + 4] = make_float4(r[4], r[5], r[6], r[7]);
    __syncthreads();
    int c = threadIdx.x;
    float acc = 0.f;
    #pragma unroll
    for (int w = 0; w < 8; w++) acc += s_ws[w][c];
    atomicAdd(&g_pooled[b*DM + c], acc);
}

// ---------------- causal depthwise conv (k=4) + silu, 4 timesteps/thread ----------------
__global__ void conv_silu_kernel(const float* __restrict__ cw, const float* __restrict__ cb){
    int i = blockIdx.x*256 + threadIdx.x;
    int d  = i & (DI-1);
    int g4 = i >> 9;
    int m0 = g4 * 4;
    int t0 = m0 & (Tsz-1);
    float w0 = cw[d*4+0], w1 = cw[d*4+1], w2 = cw[d*4+2], w3 = cw[d*4+3];
    float bias = cb[d];
    float xv[7];
    const float* src = g_xz + (size_t)m0*1024 + d;
    xv[0] = (t0 >= 3) ? src[-3*1024] : 0.f;
    xv[1] = (t0 >= 2) ? src[-2*1024] : 0.f;
    xv[2] = (t0 >= 1) ? src[-1*1024] : 0.f;
    #pragma unroll
    for (int j = 0; j < 4; j++) xv[3+j] = src[j*1024];
    #pragma unroll
    for (int k = 0; k < 4; k++){
        float a = bias;
        a = fmaf(w0, xv[k],   a);
        a = fmaf(w1, xv[k+1], a);
        a = fmaf(w2, xv[k+2], a);
        a = fmaf(w3, xv[k+3], a);
        float sv = siluf(a);
        size_t o = (size_t)(m0+k)*DI + d;
        g_xmc[o]  = sv;
        g_xm_h[o] = __float2half_rn(sv);
    }
}

// ---------------- selective scan: SHFL-free, dt_proj fused (fp32 dt from g_dbl), CH=32 ----------------
__global__ __launch_bounds__(128) void scan_kernel(
    const float* __restrict__ A_log, const float* __restrict__ Dp,
    const float* __restrict__ dt_w, const float* __restrict__ dt_b)
{
    __shared__ float s_dv [2][CH][8];
    __shared__ float s_uv [2][CH][8];
    __shared__ float s_res[2][CH][8];
    __shared__ float s_bc [2][CH][32];
    __shared__ float s_p  [CH][8][17];
    __shared__ float s_wdt[8][17];
    __shared__ float s_db[8];

    const int tid  = threadIdx.x;
    const int lane = tid & 31;
    const int warp = tid >> 5;
    const int b     = blockIdx.x >> 6;
    const int dbase = (blockIdx.x & 63) * 8;
    const int dloc  = warp*2 + (lane >> 4);
    const int d     = dbase + dloc;
    const int n     = lane & 15;

    const float a  = -expf(A_log[d*DS + n]);
    const size_t base = (size_t)b * Tsz;

    const int lt = tid >> 3;
    const int ld = tid & 7;
    const int bt = tid >> 5;
    const int bcc = tid & 31;
    const float DdR = Dp[dbase + ld];

    {
        int dd = tid >> 4, kk = tid & 15;
        s_wdt[dd][kk] = dt_w[(dbase + dd)*16 + kk];
        if (tid < 8) s_db[tid] = dt_b[dbase + tid];
    }
    __syncthreads();

    auto calc_dv = [&](size_t row)->float{
        const float4* dp = (const float4*)(g_dbl + row*48);
        float s = s_db[ld];
        #pragma unroll
        for (int k = 0; k < 4; k++){
            float4 v = dp[k];
            s = fmaf(v.x, s_wdt[ld][4*k],   s);
            s = fmaf(v.y, s_wdt[ld][4*k+1], s);
            s = fmaf(v.z, s_wdt[ld][4*k+2], s);
            s = fmaf(v.w, s_wdt[ld][4*k+3], s);
        }
        return softplusf(s);
    };

    {
        #pragma unroll
        for (int hh = 0; hh < 2; hh++){
            int rr = lt + hh*16;
            size_t row = base + rr;
            s_dv [0][rr][ld] = calc_dv(row);
            s_uv [0][rr][ld] = g_xmc[row*DI + dbase + ld];
            s_res[0][rr][ld] = g_xz [row*1024 + 512 + dbase + ld];
        }
        #pragma unroll
        for (int r = 0; r < 8; r++)
            s_bc[0][bt + r*4][bcc] = g_dbl[(base + bt + r*4)*48 + 16 + bcc];
    }
    __syncthreads();

    float h = 0.f;
    int buf = 0;
    for (int tcb = 0; tcb < Tsz; tcb += CH){
        const bool more = (tcb + CH) < Tsz;
        float r_dv[2], r_uv[2], r_res[2], r_bc[8];
        if (more){
            #pragma unroll
            for (int hh = 0; hh < 2; hh++){
                size_t row = base + tcb + CH + lt + hh*16;
                r_dv[hh]  = calc_dv(row);
                r_uv[hh]  = g_xmc[row*DI + dbase + ld];
                r_res[hh] = g_xz [row*1024 + 512 + dbase + ld];
            }
            #pragma unroll
            for (int r = 0; r < 8; r++)
                r_bc[r] = g_dbl[(base + tcb + CH + bt + r*4)*48 + 16 + bcc];
        }
        #pragma unroll
        for (int i = 0; i < CH; i++){
            float dv = s_dv[buf][i][dloc];
            float uv = s_uv[buf][i][dloc];
            float Bn = s_bc[buf][i][n];
            float Cn = s_bc[buf][i][16 + n];
            float dA = __expf(dv * a);
            h = fmaf(dA, h, dv * Bn * uv);
            s_p[i][dloc][n] = h * Cn;
        }
        __syncthreads();
        #pragma unroll
        for (int hh = 0; hh < 2; hh++){
            int rr = lt + hh*16;
            float s = 0.f;
            #pragma unroll
            for (int k = 0; k < 16; k++) s += s_p[rr][ld][k];
            float uv = s_uv[buf][rr][ld];
            float rv = s_res[buf][rr][ld];
            float yv = fmaf(uv, DdR, s) * siluf(rv);
            g_y_h[(base + tcb + rr)*DI + dbase + ld] = __float2half_rn(yv);
        }
        if (more){
            int nb = buf ^ 1;
            #pragma unroll
            for (int hh = 0; hh < 2; hh++){
                int rr = lt + hh*16;
                s_dv [nb][rr][ld] = r_dv[hh];
                s_uv [nb][rr][ld] = r_uv[hh];
                s_res[nb][rr][ld] = r_res[hh];
            }
            #pragma unroll
            for (int r = 0; r < 8; r++)
                s_bc[nb][bt + r*4][bcc] = r_bc[r];
        }
        __syncthreads();
        buf ^= 1;
    }
}

// ---------------- classifier head (reads pooled sums) ----------------
__global__ __launch_bounds__(256) void fine_kernel(
    const float* __restrict__ fw, const float* __restrict__ fb,
    float* __restrict__ out)
{
    int b = blockIdx.x;
    int tid = threadIdx.x;
    int nn = tid >> 2;
    int q  = tid & 3;
    if (nn < NCLS){
        const float* wr = fw + nn*DM + q*64;
        const float* pr = g_pooled + b*DM + q*64;
        float s = 0.f;
        #pragma unroll
        for (int k = 0; k < 64; k++) s = fmaf(pr[k], wr[k], s);
        s += __shfl_xor_sync(0xffffffffu, s, 1);
        s += __shfl_xor_sync(0xffffffffu, s, 2);
        if (q == 0) out[b*NCLS + nn] = s * (1.f/1024.f) + fb[nn];
    }
}

// ---------------- launch ----------------
extern "C" void kernel_launch(void* const* d_in, const int* in_sizes, int n_in,
                              void* d_out, int out_size)
{
    const float* x          = (const float*)d_in[0];
    const float* embed_w    = (const float*)d_in[1];
    const float* embed_b    = (const float*)d_in[2];
    const float* pre_g      = (const float*)d_in[3];
    const float* pre_b      = (const float*)d_in[4];
    const float* in_proj_w  = (const float*)d_in[5];
    const float* conv_w     = (const float*)d_in[6];
    const float* conv_b     = (const float*)d_in[7];
    const float* x_proj_w   = (const float*)d_in[8];
    const float* dt_proj_w  = (const float*)d_in[9];
    const float* dt_proj_b  = (const float*)d_in[10];
    const float* A_log      = (const float*)d_in[11];
    const float* Dp         = (const float*)d_in[12];
    const float* out_proj_w = (const float*)d_in[13];
    const float* post_g     = (const float*)d_in[14];
    const float* post_b     = (const float*)d_in[15];
    const float* fine_w     = (const float*)d_in[16];
    const float* fine_b     = (const float*)d_in[17];
    float* out = (float*)d_out;

    void *p_fk,*p_feat,*p_hnh,*p_xz,*p_xmh,*p_dbl,*p_yh,
         *p_wembh,*p_wembl,*p_winh,*p_winl,*p_wxph,*p_wxpl,*p_wouth,*p_woutl;
    cudaGetSymbolAddress(&p_fk, g_fk_h);
    cudaGetSymbolAddress(&p_feat, g_feat);
    cudaGetSymbolAddress(&p_hnh, g_hn_h);
    cudaGetSymbolAddress(&p_xz, g_xz);       cudaGetSymbolAddress(&p_xmh, g_xm_h);
    cudaGetSymbolAddress(&p_dbl, g_dbl);
    cudaGetSymbolAddress(&p_yh, g_y_h);
    cudaGetSymbolAddress(&p_wembh, g_wemb_h); cudaGetSymbolAddress(&p_wembl, g_wemb_l);
    cudaGetSymbolAddress(&p_winh, g_win_h);   cudaGetSymbolAddress(&p_winl, g_win_l);
    cudaGetSymbolAddress(&p_wxph, g_wxp_h);   cudaGetSymbolAddress(&p_wxpl, g_wxp_l);
    cudaGetSymbolAddress(&p_wouth, g_wout_h); cudaGetSymbolAddress(&p_woutl, g_wout_l);

    const int SM_G128 = 2 * ((128 + 128)*(64+8)) * 2;  // 73728 B
    const int SM_G64  = 2 * ((64  + 128)*(64+8)) * 2;  // 55296 B
    cudaFuncSetAttribute(gemm_h<128,64,64>, cudaFuncAttributeMaxDynamicSharedMemorySize, SM_G128);
    cudaFuncSetAttribute(gemm_h<64,64,64>,  cudaFuncAttributeMaxDynamicSharedMemorySize, SM_G64);

    // 1) merged prep (weight splits + features + zero fills)
    prep_kernel<<<3105, 256>>>(x, embed_w, in_proj_w, x_proj_w, out_proj_w);

    // 2) embed GEMM (MT=64: 512 CTAs)
    gemm_h<64,64,64><<<dim3(DM/64, Msz/64), 256, SM_G64>>>(
        KF, DM,
        (const __half*)p_fk, KF,
        (const __half*)p_wembh, (const __half*)p_wembl, KF,
        (float*)p_feat, DM, embed_b, nullptr, 0, 0, 1);

    // 3) pre-LN -> fp16
    ln_kernel<<<Msz/8, 256>>>((const float*)p_feat, pre_g, pre_b, (__half*)p_hnh);

    // 4) in_proj GEMM (MT=128, KC=64; ncu capture slot)
    gemm_h<128,64,64><<<dim3(1024/64, Msz/128), 256, SM_G128>>>(
        DM, 1024,
        (const __half*)p_hnh, DM,
        (const __half*)p_winh, (const __half*)p_winl, DM,
        (float*)p_xz, 1024, nullptr, nullptr, 0, 0, 1);

    // 5) depthwise conv + silu (4 timesteps/thread)
    conv_silu_kernel<<<(Msz/4)*DI/256, 256>>>(conv_w, conv_b);

    // 6) x_proj GEMM split-K=4 (atomic accumulate into zeroed g_dbl)
    gemm_h<64,64,64><<<dim3(1, Msz/64, 4), 256, SM_G64>>>(
        128, 48,
        (const __half*)p_xmh, DI,
        (const __half*)p_wxph, (const __half*)p_wxpl, DI,
        (float*)p_dbl, 48, nullptr, nullptr, 0, 0, 4);

    // 7) selective scan (dt_proj fp32 + softplus + gate fused, SHFL-free, CH=32)
    scan_kernel<<<Bsz*64, 128>>>(A_log, Dp, dt_proj_w, dt_proj_b);

    // 8) out_proj GEMM split-K=2: atomicAdd directly into g_feat (residual base)
    gemm_h<64,64,64><<<dim3(DM/64, Msz/64, 2), 256, SM_G64>>>(
        256, DM,
        (const __half*)p_yh, DI,
        (const __half*)p_wouth, (const __half*)p_woutl, DI,
        (float*)p_feat, DM, nullptr, nullptr, 0, 0, 2);

    // 9) fused post-LN + mean-pool (atomic accumulate into g_pooled)
    lnpool_kernel<<<Msz/8, 256>>>((const float*)p_feat, post_g, post_b);

    // 10) classifier
    fine_kernel<<<Bsz, 256>>>(fine_w, fine_b, out);

    (void)in_sizes; (void)n_in; (void)out_size;
}